// round 13
// baseline (speedup 1.0000x reference)
#include <cuda_runtime.h>
#include <cuda_bf16.h>
#include <math.h>
#include <stdint.h>

#define NB 2
#define NT 2048
#define NC 1024
#define NH 16
#define ND 64
#define NBH (NB*NH)
#define NM (NB*NT)   // 4096 rows

// ---------------------------------------------------------------------------
// Scratch (static device allocations)
// ---------------------------------------------------------------------------
__device__ __nv_bfloat16 g_qkvh[(size_t)NM * 3 * NC];   // QKV gemm out hi/lo
__device__ __nv_bfloat16 g_qkvl[(size_t)NM * 3 * NC];

__device__ __nv_bfloat16 g_xh[(size_t)NM * NC];         // x hi/lo
__device__ __nv_bfloat16 g_xl[(size_t)NM * NC];
__device__ __nv_bfloat16 g_yh[(size_t)NM * NC];         // attn out hi/lo
__device__ __nv_bfloat16 g_yl[(size_t)NM * NC];
__device__ __nv_bfloat16 g_wah[(size_t)(3*NC) * NC];    // Wa^T hi/lo [3072][1024]
__device__ __nv_bfloat16 g_wal[(size_t)(3*NC) * NC];
__device__ __nv_bfloat16 g_wph[(size_t)NC * NC];        // Wp^T hi/lo
__device__ __nv_bfloat16 g_wpl[(size_t)NC * NC];

__device__ __nv_bfloat16 g_qh[(size_t)NBH * NT * ND];   // RoPE'd Q*scale hi/lo
__device__ __nv_bfloat16 g_ql[(size_t)NBH * NT * ND];
__device__ __nv_bfloat16 g_kh[(size_t)NBH * NT * ND];
__device__ __nv_bfloat16 g_kl[(size_t)NBH * NT * ND];
__device__ __nv_bfloat16 g_vh[(size_t)NBH * NT * ND];
__device__ __nv_bfloat16 g_vl[(size_t)NBH * NT * ND];

// ---------------------------------------------------------------------------
__device__ __forceinline__ uint32_t smem_u32(const void* p) {
    uint32_t a;
    asm("{ .reg .u64 t; cvta.to.shared.u64 t, %1; cvt.u32.u64 %0, t; }"
        : "=r"(a) : "l"(p));
    return a;
}
#define SWZ(o)   ((o) ^ (((o) >> 3) & 0x70))   // SW128 (128B rows)
#define SWZ64(o) ((o) ^ (((o) >> 3) & 0x30))   // SW64  (64B rows)

__device__ __forceinline__ void cpa16(uint32_t dst, const void* src) {
    asm volatile("cp.async.cg.shared.global [%0], [%1], 16;"
                 :: "r"(dst), "l"(src) : "memory");
}
#define CP_COMMIT() asm volatile("cp.async.commit_group;" ::: "memory")
#define CP_WAIT1()  asm volatile("cp.async.wait_group 1;" ::: "memory")
#define CP_WAIT0()  asm volatile("cp.async.wait_group 0;" ::: "memory")

__device__ __forceinline__ void ldsm4(uint32_t* r, uint32_t addr) {
    asm volatile("ldmatrix.sync.aligned.m8n8.x4.shared.b16 {%0,%1,%2,%3}, [%4];"
                 : "=r"(r[0]), "=r"(r[1]), "=r"(r[2]), "=r"(r[3]) : "r"(addr));
}
__device__ __forceinline__ void ldsm4t(uint32_t* r, uint32_t addr) {
    asm volatile("ldmatrix.sync.aligned.m8n8.x4.trans.shared.b16 {%0,%1,%2,%3}, [%4];"
                 : "=r"(r[0]), "=r"(r[1]), "=r"(r[2]), "=r"(r[3]) : "r"(addr));
}
__device__ __forceinline__ void mma16816(float* d, const uint32_t* a, const uint32_t* b) {
    asm volatile(
        "mma.sync.aligned.m16n8k16.row.col.f32.bf16.bf16.f32 "
        "{%0,%1,%2,%3}, {%4,%5,%6,%7}, {%8,%9}, {%0,%1,%2,%3};"
        : "+f"(d[0]), "+f"(d[1]), "+f"(d[2]), "+f"(d[3])
        : "r"(a[0]), "r"(a[1]), "r"(a[2]), "r"(a[3]), "r"(b[0]), "r"(b[1]));
}
__device__ __forceinline__ uint32_t packf(float lo, float hi) {
    uint32_t d;
    asm("cvt.rn.bf16x2.f32 %0, %1, %2;" : "=r"(d) : "f"(hi), "f"(lo));
    return d;
}

// ---------------------------------------------------------------------------
// Elementwise fp32 -> bf16 hi/lo split
// ---------------------------------------------------------------------------
__global__ void cvt_split(const float* __restrict__ in,
                          __nv_bfloat16* __restrict__ h,
                          __nv_bfloat16* __restrict__ l) {
    int i = (blockIdx.x * blockDim.x + threadIdx.x) * 4;
    float4 a = *(const float4*)(in + i);
    float v[4] = {a.x, a.y, a.z, a.w};
    __nv_bfloat16 hh[4], ll[4];
#pragma unroll
    for (int j = 0; j < 4; j++) {
        hh[j] = __float2bfloat16(v[j]);
        ll[j] = __float2bfloat16(v[j] - __bfloat162float(hh[j]));
    }
    *(__nv_bfloat162*)(h + i)     = *(__nv_bfloat162*)&hh[0];
    *(__nv_bfloat162*)(h + i + 2) = *(__nv_bfloat162*)&hh[2];
    *(__nv_bfloat162*)(l + i)     = *(__nv_bfloat162*)&ll[0];
    *(__nv_bfloat162*)(l + i + 2) = *(__nv_bfloat162*)&ll[2];
}

// ---------------------------------------------------------------------------
// W [K][N] fp32 -> W^T hi/lo [N][K] bf16
// ---------------------------------------------------------------------------
__global__ void wt_split(const float* __restrict__ W,
                         __nv_bfloat16* __restrict__ Th,
                         __nv_bfloat16* __restrict__ Tl, int K, int N) {
    __shared__ float t[32][33];
    int n0 = blockIdx.x * 32, k0 = blockIdx.y * 32;
    int tx = threadIdx.x, ty0 = threadIdx.y;
#pragma unroll
    for (int i = 0; i < 4; i++) {
        int ty = ty0 + i * 8;
        t[ty][tx] = W[(size_t)(k0 + ty) * N + n0 + tx];
    }
    __syncthreads();
#pragma unroll
    for (int i = 0; i < 4; i++) {
        int ty = ty0 + i * 8;
        float a = t[tx][ty];
        __nv_bfloat16 h = __float2bfloat16(a);
        __nv_bfloat16 l = __float2bfloat16(a - __bfloat162float(h));
        Th[(size_t)(n0 + ty) * K + k0 + tx] = h;
        Tl[(size_t)(n0 + ty) * K + k0 + tx] = l;
    }
}

// ---------------------------------------------------------------------------
// HMMA bf16x3 GEMM: CTA 128x128, 4 warps (warp tile 64x64), 3-stage cp.async.
// Epilogue: Ch==nullptr -> fp32 to C; else bf16 hi/lo pairs to Ch/Cl [M][N].
// ---------------------------------------------------------------------------
__global__ __launch_bounds__(128, 2) void gemm_mma(
    const __nv_bfloat16* __restrict__ Ah, const __nv_bfloat16* __restrict__ Al,
    const __nv_bfloat16* __restrict__ Bh, const __nv_bfloat16* __restrict__ Bl,
    float* __restrict__ C,
    __nv_bfloat16* __restrict__ Ch, __nv_bfloat16* __restrict__ Cl,
    int M, int N, int K) {
    extern __shared__ char smem[];
    const uint32_t sb = smem_u32(smem);   // stage s at sb + s*32768
    const int tid = threadIdx.x, wid = tid >> 5, lane = tid & 31;
    const int m0 = blockIdx.y * 128, n0 = blockIdx.x * 128;
    const int wm0 = (wid >> 1) * 64, wn0 = (wid & 1) * 64;

    const __nv_bfloat16* bA0 = Ah + (size_t)m0 * K;
    const __nv_bfloat16* bA1 = Al + (size_t)m0 * K;
    const __nv_bfloat16* bB0 = Bh + (size_t)n0 * K;
    const __nv_bfloat16* bB1 = Bl + (size_t)n0 * K;

    uint32_t a_r[4], a_z[4];
#pragma unroll
    for (int i = 0; i < 4; i++) {
        int row = wm0 + 16 * i + (lane & 15);
        a_r[i] = row * 64;
        a_z[i] = (row & 6) << 3;
    }
    const uint32_t gA = (lane >> 4) * 16;
    uint32_t b_r[4], b_z[4];
#pragma unroll
    for (int j = 0; j < 4; j++) {
        int row = wn0 + 16 * j + (lane & 7) + ((lane >> 4) << 3);
        b_r[j] = row * 64;
        b_z[j] = (row & 6) << 3;
    }
    const uint32_t gB = ((lane >> 3) & 1) * 16;

    float acc[4][8][4];
#pragma unroll
    for (int i = 0; i < 4; i++)
#pragma unroll
        for (int j = 0; j < 8; j++)
#pragma unroll
            for (int q = 0; q < 4; q++) acc[i][j][q] = 0.f;

#define G_ISSUE(cc, ss)                                                        \
    do {                                                                       \
        const int k0_ = (cc) * 32;                                             \
        const uint32_t stb_ = sb + (ss) * 32768;                               \
        _Pragma("unroll")                                                      \
        for (int i_ = 0; i_ < 16; i_++) {                                      \
            const __nv_bfloat16* base_ =                                       \
                (i_ >> 2) == 0 ? bA0 : (i_ >> 2) == 1 ? bA1                    \
              : (i_ >> 2) == 2 ? bB0 : bB1;                                    \
            int w_ = tid + (i_ & 3) * 128;                                     \
            int r_ = w_ >> 2, c4_ = w_ & 3;                                    \
            cpa16(stb_ + (i_ >> 2) * 8192 + SWZ64(r_ * 64 + c4_ * 16),         \
                  base_ + (size_t)r_ * K + k0_ + c4_ * 8);                     \
        }                                                                      \
        CP_COMMIT();                                                           \
    } while (0)

    const int nch = K / 32;
    G_ISSUE(0, 0);
    G_ISSUE(1, 1);
    int s = 0;
    for (int c = 0; c < nch; c++) {
        if (c + 1 < nch) CP_WAIT1(); else CP_WAIT0();
        __syncthreads();
        if (c + 2 < nch) G_ISSUE(c + 2, (s + 2) % 3);

        const uint32_t stb = sb + s * 32768;
#pragma unroll
        for (int ks = 0; ks < 2; ks++) {
            const uint32_t off = ks * 32;
            uint32_t af[4][4], bh2[4][4], bl2[4][4];
#pragma unroll
            for (int i = 0; i < 4; i++)
                ldsm4(af[i], stb + a_r[i] + ((off + gA) ^ a_z[i]));
#pragma unroll
            for (int j = 0; j < 4; j++) {
                ldsm4(bh2[j], stb + 16384 + b_r[j] + ((off + gB) ^ b_z[j]));
                ldsm4(bl2[j], stb + 24576 + b_r[j] + ((off + gB) ^ b_z[j]));
            }
#pragma unroll
            for (int i = 0; i < 4; i++)
#pragma unroll
                for (int j = 0; j < 4; j++) {
                    mma16816(acc[i][j * 2 + 0], af[i], &bh2[j][0]);
                    mma16816(acc[i][j * 2 + 1], af[i], &bh2[j][2]);
                }
#pragma unroll
            for (int i = 0; i < 4; i++)
#pragma unroll
                for (int j = 0; j < 4; j++) {
                    mma16816(acc[i][j * 2 + 0], af[i], &bl2[j][0]);
                    mma16816(acc[i][j * 2 + 1], af[i], &bl2[j][2]);
                }
#pragma unroll
            for (int i = 0; i < 4; i++)
                ldsm4(af[i], stb + 8192 + a_r[i] + ((off + gA) ^ a_z[i]));
#pragma unroll
            for (int i = 0; i < 4; i++)
#pragma unroll
                for (int j = 0; j < 4; j++) {
                    mma16816(acc[i][j * 2 + 0], af[i], &bh2[j][0]);
                    mma16816(acc[i][j * 2 + 1], af[i], &bh2[j][2]);
                }
        }
        s = (s + 1) % 3;
    }
#undef G_ISSUE

    const int er = lane >> 2, ec = (lane & 3) * 2;
    if (Ch == nullptr) {
#pragma unroll
        for (int i = 0; i < 4; i++) {
            int r = m0 + wm0 + 16 * i + er;
#pragma unroll
            for (int j = 0; j < 8; j++) {
                int col = n0 + wn0 + 8 * j + ec;
                *(float2*)(C + (size_t)r * N + col)       = make_float2(acc[i][j][0], acc[i][j][1]);
                *(float2*)(C + (size_t)(r + 8) * N + col) = make_float2(acc[i][j][2], acc[i][j][3]);
            }
        }
    } else {
#pragma unroll
        for (int i = 0; i < 4; i++) {
            int r = m0 + wm0 + 16 * i + er;
#pragma unroll
            for (int j = 0; j < 8; j++) {
                int col = n0 + wn0 + 8 * j + ec;
                float v0 = acc[i][j][0], v1 = acc[i][j][1];
                float v2 = acc[i][j][2], v3 = acc[i][j][3];
                uint32_t ph0 = packf(v0, v1), ph1 = packf(v2, v3);
                uint32_t pl0 = packf(v0 - __uint_as_float(ph0 << 16),
                                     v1 - __uint_as_float(ph0 & 0xffff0000u));
                uint32_t pl1 = packf(v2 - __uint_as_float(ph1 << 16),
                                     v3 - __uint_as_float(ph1 & 0xffff0000u));
                *(uint32_t*)(Ch + (size_t)r * N + col)       = ph0;
                *(uint32_t*)(Cl + (size_t)r * N + col)       = pl0;
                *(uint32_t*)(Ch + (size_t)(r + 8) * N + col) = ph1;
                *(uint32_t*)(Cl + (size_t)(r + 8) * N + col) = pl1;
            }
        }
    }
}

// ---------------------------------------------------------------------------
// RoPE + head split from bf16 hi/lo qkv; one thread per d-pair.
// q_out[d] = q[d]*cos + q[(d-1)%64]*sin ; Q also scaled by 0.125.
// V hi/lo pass through unchanged.
// ---------------------------------------------------------------------------
__global__ void rope_split(const __nv_bfloat16* __restrict__ qkvh,
                           const __nv_bfloat16* __restrict__ qkvl)
{
    int idx = blockIdx.x * blockDim.x + threadIdx.x;  // over BH*T*32
    int p  = idx & 31;
    int t  = (idx >> 5) & (NT - 1);
    int bh = idx >> 16;
    int b = bh >> 4, h = bh & (NH - 1);
    int d0 = p * 2;
    int dm = (d0 + 62) & 63;           // pair holding partner d0-1 in .y
    size_t row = (size_t)(b * NT + t) * (3 * NC);
    int cq = h * ND;

#define LD2(arr, c) (*(const __nv_bfloat162*)((arr) + row + (c)))
    __nv_bfloat162 qhp = LD2(qkvh, cq + d0),      qlp = LD2(qkvl, cq + d0);
    __nv_bfloat162 qhm = LD2(qkvh, cq + dm),      qlm = LD2(qkvl, cq + dm);
    __nv_bfloat162 khp = LD2(qkvh, NC + cq + d0), klp = LD2(qkvl, NC + cq + d0);
    __nv_bfloat162 khm = LD2(qkvh, NC + cq + dm), klm = LD2(qkvl, NC + cq + dm);
    __nv_bfloat162 vhp = LD2(qkvh, 2*NC + cq + d0), vlp = LD2(qkvl, 2*NC + cq + d0);
#undef LD2

    float q0 = __bfloat162float(qhp.x) + __bfloat162float(qlp.x);
    float q1 = __bfloat162float(qhp.y) + __bfloat162float(qlp.y);
    float qm1 = __bfloat162float(qhm.y) + __bfloat162float(qlm.y);
    float k0 = __bfloat162float(khp.x) + __bfloat162float(klp.x);
    float k1 = __bfloat162float(khp.y) + __bfloat162float(klp.y);
    float km1 = __bfloat162float(khm.y) + __bfloat162float(klm.y);

    int fi0 = d0 & 31, fi1 = (d0 + 1) & 31;
    float iv0 = expf(-(float)fi0 * (9.210340371976184f / 32.0f));
    float iv1 = expf(-(float)fi1 * (9.210340371976184f / 32.0f));
    float sn0, cs0, sn1, cs1;
    sincosf((float)t * iv0, &sn0, &cs0);
    sincosf((float)t * iv1, &sn1, &cs1);

    float rq0 = (q0 * cs0 + qm1 * sn0) * 0.125f;
    float rq1 = (q1 * cs1 + q0  * sn1) * 0.125f;
    float rk0 = k0 * cs0 + km1 * sn0;
    float rk1 = k1 * cs1 + k0  * sn1;

    size_t o = ((size_t)bh * NT + t) * ND + d0;
    uint32_t ph, pl;
    ph = packf(rq0, rq1);
    pl = packf(rq0 - __uint_as_float(ph << 16), rq1 - __uint_as_float(ph & 0xffff0000u));
    *(uint32_t*)(g_qh + o) = ph;
    *(uint32_t*)(g_ql + o) = pl;
    ph = packf(rk0, rk1);
    pl = packf(rk0 - __uint_as_float(ph << 16), rk1 - __uint_as_float(ph & 0xffff0000u));
    *(uint32_t*)(g_kh + o) = ph;
    *(uint32_t*)(g_kl + o) = pl;
    *(__nv_bfloat162*)(g_vh + o) = vhp;
    *(__nv_bfloat162*)(g_vl + o) = vlp;
}

// ---------------------------------------------------------------------------
// Flash attention on HMMA, cp.async double-buffered K/V tiles. LPT order.
// smem: Q hi/lo 32KB @ sb; KV stages 32KB each @ sb+32768 + s*32768.
// ---------------------------------------------------------------------------
__global__ __launch_bounds__(256, 2) void flash_mma(
    const __nv_bfloat16* __restrict__ Qh_, const __nv_bfloat16* __restrict__ Ql_,
    const __nv_bfloat16* __restrict__ Kh_, const __nv_bfloat16* __restrict__ Kl_,
    const __nv_bfloat16* __restrict__ Vh_, const __nv_bfloat16* __restrict__ Vl_,
    __nv_bfloat16* __restrict__ Yh_, __nv_bfloat16* __restrict__ Yl_)
{
    extern __shared__ char smem[];
    const uint32_t sb = smem_u32(smem);
    const uint32_t sQh = sb, sQl = sb + 16384;

    const int bh = blockIdx.y;
    const int qi = (gridDim.x - 1) - blockIdx.x;   // LPT: heaviest first
    const int q0 = qi * 128;
    const int tid = threadIdx.x, wid = tid >> 5, lane = tid & 31;
    const int wm = wid * 16;
    const size_t gbase = (size_t)bh * NT * ND;

    const __nv_bfloat16* pKh = Kh_ + gbase;
    const __nv_bfloat16* pKl = Kl_ + gbase;
    const __nv_bfloat16* pVh = Vh_ + gbase;
    const __nv_bfloat16* pVl = Vl_ + gbase;

    // ---- load Q hi/lo (128x64, SW128) ----
    {
        const __nv_bfloat16* s0 = Qh_ + gbase + (size_t)q0 * ND;
        const __nv_bfloat16* s1 = Ql_ + gbase + (size_t)q0 * ND;
#pragma unroll
        for (int i = 0; i < 4; i++) {
            int idx = tid + i * 256;
            int r = idx >> 3, c8 = idx & 7;
            uint32_t off = SWZ(r * 128 + c8 * 16);
            uint4 v = *(const uint4*)(s0 + (size_t)r * ND + c8 * 8);
            asm volatile("st.shared.v4.b32 [%0], {%1,%2,%3,%4};"
                         :: "r"(sQh + off), "r"(v.x), "r"(v.y), "r"(v.z), "r"(v.w));
            uint4 w = *(const uint4*)(s1 + (size_t)r * ND + c8 * 8);
            asm volatile("st.shared.v4.b32 [%0], {%1,%2,%3,%4};"
                         :: "r"(sQl + off), "r"(w.x), "r"(w.y), "r"(w.z), "r"(w.w));
        }
    }

#define F_ISSUE(kt_, ss)                                                       \
    do {                                                                       \
        const size_t ko_ = (size_t)(kt_) * 64 * ND;                            \
        const uint32_t kvb_ = sb + 32768 + (ss) * 32768;                       \
        _Pragma("unroll")                                                      \
        for (int i_ = 0; i_ < 8; i_++) {                                       \
            const __nv_bfloat16* base_ =                                       \
                (i_ >> 1) == 0 ? pKh : (i_ >> 1) == 1 ? pKl                    \
              : (i_ >> 1) == 2 ? pVh : pVl;                                    \
            int w_ = tid + (i_ & 1) * 256;                                     \
            int r_ = w_ >> 3, c8_ = w_ & 7;                                    \
            cpa16(kvb_ + (i_ >> 1) * 8192 + SWZ(r_ * 128 + c8_ * 16),          \
                  base_ + ko_ + (size_t)r_ * ND + c8_ * 8);                    \
        }                                                                      \
        CP_COMMIT();                                                           \
    } while (0)

    const int rowA = wm + (lane & 15);
    const uint32_t aoff = rowA * 128, aswz = (rowA & 7) * 16;
    const uint32_t gA = (lane >> 4) * 16;
    const int rowB_ = (lane & 7) + ((lane >> 4) << 3);
    const uint32_t bswz = (rowB_ & 7) * 16;
    const uint32_t gB = ((lane >> 3) & 1) * 16;
    const int rowV_ = ((lane >> 3) & 1) * 8 + (lane & 7);
    const uint32_t vswz = (lane & 7) * 16;
    const uint32_t gV = (lane >> 4) * 16;

    float m0 = -1e30f, m1 = -1e30f, l0 = 0.f, l1 = 0.f;
    float oacc[8][4];
#pragma unroll
    for (int j = 0; j < 8; j++)
#pragma unroll
        for (int e = 0; e < 4; e++) oacc[j][e] = 0.f;

    const int nkt = 2 * qi + 2;
    F_ISSUE(0, 0);
    for (int kt = 0; kt < nkt; kt++) {
        const int s = kt & 1;
        if (kt + 1 < nkt) { F_ISSUE(kt + 1, s ^ 1); CP_WAIT1(); }
        else              { CP_WAIT0(); }
        __syncthreads();

        const uint32_t kvb = sb + 32768 + s * 32768;
        const uint32_t sKh = kvb, sKl = kvb + 8192;
        const uint32_t sVh = kvb + 16384, sVl = kvb + 24576;

        if (kt * 64 <= q0 + wm + 15) {
            float sacc[8][4];
#pragma unroll
            for (int j = 0; j < 8; j++)
#pragma unroll
                for (int e = 0; e < 4; e++) sacc[j][e] = 0.f;

#pragma unroll
            for (int ks = 0; ks < 4; ks++) {
                const uint32_t ks32 = ks * 32;
                uint32_t aqh[4], aql[4];
                ldsm4(aqh, sQh + aoff + ((ks32 + gA) ^ aswz));
                ldsm4(aql, sQl + aoff + ((ks32 + gA) ^ aswz));
#pragma unroll
                for (int jb = 0; jb < 4; jb++) {
                    uint32_t roff = (jb * 16 + rowB_) * 128 + ((ks32 + gB) ^ bswz);
                    uint32_t kh4[4], kl4[4];
                    ldsm4(kh4, sKh + roff);
                    ldsm4(kl4, sKl + roff);
                    mma16816(sacc[2 * jb + 0], aqh, &kh4[0]);
                    mma16816(sacc[2 * jb + 1], aqh, &kh4[2]);
                    mma16816(sacc[2 * jb + 0], aqh, &kl4[0]);
                    mma16816(sacc[2 * jb + 1], aqh, &kl4[2]);
                    mma16816(sacc[2 * jb + 0], aql, &kh4[0]);
                    mma16816(sacc[2 * jb + 1], aql, &kh4[2]);
                }
            }

            if ((kt + 1) * 64 - 1 > q0 + wm) {
                const int rb = q0 + wm + (lane >> 2);
                const int cb = kt * 64 + (lane & 3) * 2;
#pragma unroll
                for (int t = 0; t < 8; t++) {
                    int c = cb + t * 8;
                    if (c     > rb)     sacc[t][0] = -1e30f;
                    if (c + 1 > rb)     sacc[t][1] = -1e30f;
                    if (c     > rb + 8) sacc[t][2] = -1e30f;
                    if (c + 1 > rb + 8) sacc[t][3] = -1e30f;
                }
            }

            {
                float mx0 = -1e30f, mx1 = -1e30f;
#pragma unroll
                for (int t = 0; t < 8; t++) {
                    mx0 = fmaxf(mx0, fmaxf(sacc[t][0], sacc[t][1]));
                    mx1 = fmaxf(mx1, fmaxf(sacc[t][2], sacc[t][3]));
                }
                mx0 = fmaxf(mx0, __shfl_xor_sync(0xffffffffu, mx0, 1));
                mx0 = fmaxf(mx0, __shfl_xor_sync(0xffffffffu, mx0, 2));
                mx1 = fmaxf(mx1, __shfl_xor_sync(0xffffffffu, mx1, 1));
                mx1 = fmaxf(mx1, __shfl_xor_sync(0xffffffffu, mx1, 2));
                float mn0 = fmaxf(m0, mx0), mn1 = fmaxf(m1, mx1);
                float a0 = __expf(m0 - mn0), a1 = __expf(m1 - mn1);
                m0 = mn0; m1 = mn1;
                float ls0 = 0.f, ls1 = 0.f;
#pragma unroll
                for (int t = 0; t < 8; t++) {
                    sacc[t][0] = __expf(sacc[t][0] - mn0);
                    sacc[t][1] = __expf(sacc[t][1] - mn0);
                    sacc[t][2] = __expf(sacc[t][2] - mn1);
                    sacc[t][3] = __expf(sacc[t][3] - mn1);
                    ls0 += sacc[t][0] + sacc[t][1];
                    ls1 += sacc[t][2] + sacc[t][3];
                }
                ls0 += __shfl_xor_sync(0xffffffffu, ls0, 1);
                ls0 += __shfl_xor_sync(0xffffffffu, ls0, 2);
                ls1 += __shfl_xor_sync(0xffffffffu, ls1, 1);
                ls1 += __shfl_xor_sync(0xffffffffu, ls1, 2);
                l0 = l0 * a0 + ls0;
                l1 = l1 * a1 + ls1;
#pragma unroll
                for (int j = 0; j < 8; j++) {
                    oacc[j][0] *= a0; oacc[j][1] *= a0;
                    oacc[j][2] *= a1; oacc[j][3] *= a1;
                }
            }

#pragma unroll
            for (int ks = 0; ks < 4; ks++) {
                uint32_t ah[4], al[4];
                ah[0] = packf(sacc[2*ks][0],   sacc[2*ks][1]);
                ah[1] = packf(sacc[2*ks][2],   sacc[2*ks][3]);
                ah[2] = packf(sacc[2*ks+1][0], sacc[2*ks+1][1]);
                ah[3] = packf(sacc[2*ks+1][2], sacc[2*ks+1][3]);
#pragma unroll
                for (int r = 0; r < 4; r++) {
                    float flo = __uint_as_float(ah[r] << 16);
                    float fhi = __uint_as_float(ah[r] & 0xffff0000u);
                    float s0 = sacc[2*ks + (r >> 1)][(r & 1) * 2 + 0];
                    float s1 = sacc[2*ks + (r >> 1)][(r & 1) * 2 + 1];
                    al[r] = packf(s0 - flo, s1 - fhi);
                }
                const uint32_t vrow = (ks * 16 + rowV_) * 128;
#pragma unroll
                for (int jb = 0; jb < 4; jb++) {
                    uint32_t voff = vrow + ((jb * 32 + gV) ^ vswz);
                    uint32_t vh4[4], vl4[4];
                    ldsm4t(vh4, sVh + voff);
                    ldsm4t(vl4, sVl + voff);
                    mma16816(oacc[2 * jb + 0], ah, &vh4[0]);
                    mma16816(oacc[2 * jb + 1], ah, &vh4[2]);
                    mma16816(oacc[2 * jb + 0], ah, &vl4[0]);
                    mma16816(oacc[2 * jb + 1], ah, &vl4[2]);
                    mma16816(oacc[2 * jb + 0], al, &vh4[0]);
                    mma16816(oacc[2 * jb + 1], al, &vh4[2]);
                }
            }
        }
        __syncthreads();
    }
#undef F_ISSUE

    {
        const int b = bh >> 4, h = bh & (NH - 1);
        const float i0 = 1.f / l0, i1 = 1.f / l1;
        const int t0 = q0 + wm + (lane >> 2);
        const int c0 = h * ND + (lane & 3) * 2;
#pragma unroll
        for (int j = 0; j < 8; j++) {
            float v0 = oacc[j][0] * i0, v1 = oacc[j][1] * i0;
            float v2 = oacc[j][2] * i1, v3 = oacc[j][3] * i1;
            uint32_t ph0 = packf(v0, v1), ph1 = packf(v2, v3);
            uint32_t pl0 = packf(v0 - __uint_as_float(ph0 << 16),
                                 v1 - __uint_as_float(ph0 & 0xffff0000u));
            uint32_t pl1 = packf(v2 - __uint_as_float(ph1 << 16),
                                 v3 - __uint_as_float(ph1 & 0xffff0000u));
            size_t o0 = (size_t)(b * NT + t0) * NC + c0 + j * 8;
            size_t o1 = (size_t)(b * NT + t0 + 8) * NC + c0 + j * 8;
            *(uint32_t*)(Yh_ + o0) = ph0;
            *(uint32_t*)(Yl_ + o0) = pl0;
            *(uint32_t*)(Yh_ + o1) = ph1;
            *(uint32_t*)(Yl_ + o1) = pl1;
        }
    }
}

// ---------------------------------------------------------------------------
extern "C" void kernel_launch(void* const* d_in, const int* in_sizes, int n_in,
                              void* d_out, int out_size)
{
    const float* x  = (const float*)d_in[0];
    const float* Wa = (const float*)d_in[1];
    const float* Wp = (const float*)d_in[2];
    float* out = (float*)d_out;

    __nv_bfloat16 *qkvh, *qkvl, *xh, *xl, *yh, *yl, *wah, *wal, *wph, *wpl;
    __nv_bfloat16 *qh, *ql, *kh, *kl, *vh, *vl;
    cudaGetSymbolAddress((void**)&qkvh, g_qkvh);
    cudaGetSymbolAddress((void**)&qkvl, g_qkvl);
    cudaGetSymbolAddress((void**)&xh,  g_xh);
    cudaGetSymbolAddress((void**)&xl,  g_xl);
    cudaGetSymbolAddress((void**)&yh,  g_yh);
    cudaGetSymbolAddress((void**)&yl,  g_yl);
    cudaGetSymbolAddress((void**)&wah, g_wah);
    cudaGetSymbolAddress((void**)&wal, g_wal);
    cudaGetSymbolAddress((void**)&wph, g_wph);
    cudaGetSymbolAddress((void**)&wpl, g_wpl);
    cudaGetSymbolAddress((void**)&qh,  g_qh);
    cudaGetSymbolAddress((void**)&ql,  g_ql);
    cudaGetSymbolAddress((void**)&kh,  g_kh);
    cudaGetSymbolAddress((void**)&kl,  g_kl);
    cudaGetSymbolAddress((void**)&vh,  g_vh);
    cudaGetSymbolAddress((void**)&vl,  g_vl);

    const int gemm_smem = 98304;          // 3 stages x 32KB
    cudaFuncSetAttribute(gemm_mma, cudaFuncAttributeMaxDynamicSharedMemorySize, gemm_smem);
    const int flash_smem = 98304;         // Q 32KB + 2 stages x 32KB
    cudaFuncSetAttribute(flash_mma, cudaFuncAttributeMaxDynamicSharedMemorySize, flash_smem);

    // 0) input splits / weight transposes
    cvt_split<<<(NM * NC) / 1024, 256>>>(x, xh, xl);
    wt_split<<<dim3(3 * NC / 32, NC / 32), dim3(32, 8)>>>(Wa, wah, wal, NC, 3 * NC);
    wt_split<<<dim3(NC / 32, NC / 32), dim3(32, 8)>>>(Wp, wph, wpl, NC, NC);

    // 1) QKV = x @ W_attn -> bf16 hi/lo pairs
    gemm_mma<<<dim3(3 * NC / 128, NM / 128), 128, gemm_smem>>>(
        xh, xl, wah, wal, nullptr, qkvh, qkvl, NM, 3 * NC, NC);

    // 2) RoPE + head split (bf16 in, bf16 out)
    rope_split<<<(NBH * NT * 32) / 256, 256>>>(qkvh, qkvl);

    // 3) Flash attention (causal) on tensor cores -> yh/yl
    flash_mma<<<dim3(NT / 128, NBH), 256, flash_smem>>>(
        qh, ql, kh, kl, vh, vl, yh, yl);

    // 4) out = y @ W_proj (fp32 epilogue)
    gemm_mma<<<dim3(NC / 128, NM / 128), 128, gemm_smem>>>(
        yh, yl, wph, wpl, out, nullptr, nullptr, NM, NC, NC);
}

// round 14
// speedup vs baseline: 1.5597x; 1.5597x over previous
#include <cuda_runtime.h>
#include <cuda_bf16.h>
#include <math.h>
#include <stdint.h>

#define NB 2
#define NT 2048
#define NC 1024
#define NH 16
#define ND 64
#define NBH (NB*NH)
#define NM (NB*NT)   // 4096 rows

// ---------------------------------------------------------------------------
// Scratch (static device allocations)
// ---------------------------------------------------------------------------
__device__ float g_qkv[(size_t)NM * 3 * NC];            // [4096, 3072]

__device__ __nv_bfloat16 g_xh[(size_t)NM * NC];         // x hi/lo
__device__ __nv_bfloat16 g_xl[(size_t)NM * NC];
__device__ __nv_bfloat16 g_yh[(size_t)NM * NC];         // attn out hi/lo
__device__ __nv_bfloat16 g_yl[(size_t)NM * NC];
__device__ __nv_bfloat16 g_wah[(size_t)(3*NC) * NC];    // Wa^T hi/lo [3072][1024]
__device__ __nv_bfloat16 g_wal[(size_t)(3*NC) * NC];
__device__ __nv_bfloat16 g_wph[(size_t)NC * NC];        // Wp^T hi/lo
__device__ __nv_bfloat16 g_wpl[(size_t)NC * NC];

__device__ __nv_bfloat16 g_qh[(size_t)NBH * NT * ND];   // RoPE'd Q*scale hi/lo
__device__ __nv_bfloat16 g_ql[(size_t)NBH * NT * ND];
__device__ __nv_bfloat16 g_kh[(size_t)NBH * NT * ND];
__device__ __nv_bfloat16 g_kl[(size_t)NBH * NT * ND];
__device__ __nv_bfloat16 g_vh[(size_t)NBH * NT * ND];
__device__ __nv_bfloat16 g_vl[(size_t)NBH * NT * ND];

// ---------------------------------------------------------------------------
__device__ __forceinline__ uint32_t smem_u32(const void* p) {
    uint32_t a;
    asm("{ .reg .u64 t; cvta.to.shared.u64 t, %1; cvt.u32.u64 %0, t; }"
        : "=r"(a) : "l"(p));
    return a;
}
#define SWZ(o)   ((o) ^ (((o) >> 3) & 0x70))   // SW128 (128B rows)
#define SWZ64(o) ((o) ^ (((o) >> 3) & 0x30))   // SW64  (64B rows)

__device__ __forceinline__ void cpa16(uint32_t dst, const void* src) {
    asm volatile("cp.async.cg.shared.global [%0], [%1], 16;"
                 :: "r"(dst), "l"(src) : "memory");
}
#define CP_COMMIT() asm volatile("cp.async.commit_group;" ::: "memory")
#define CP_WAIT1()  asm volatile("cp.async.wait_group 1;" ::: "memory")
#define CP_WAIT0()  asm volatile("cp.async.wait_group 0;" ::: "memory")

__device__ __forceinline__ void ldsm4(uint32_t* r, uint32_t addr) {
    asm volatile("ldmatrix.sync.aligned.m8n8.x4.shared.b16 {%0,%1,%2,%3}, [%4];"
                 : "=r"(r[0]), "=r"(r[1]), "=r"(r[2]), "=r"(r[3]) : "r"(addr));
}
__device__ __forceinline__ void ldsm4t(uint32_t* r, uint32_t addr) {
    asm volatile("ldmatrix.sync.aligned.m8n8.x4.trans.shared.b16 {%0,%1,%2,%3}, [%4];"
                 : "=r"(r[0]), "=r"(r[1]), "=r"(r[2]), "=r"(r[3]) : "r"(addr));
}
__device__ __forceinline__ void mma16816(float* d, const uint32_t* a, const uint32_t* b) {
    asm volatile(
        "mma.sync.aligned.m16n8k16.row.col.f32.bf16.bf16.f32 "
        "{%0,%1,%2,%3}, {%4,%5,%6,%7}, {%8,%9}, {%0,%1,%2,%3};"
        : "+f"(d[0]), "+f"(d[1]), "+f"(d[2]), "+f"(d[3])
        : "r"(a[0]), "r"(a[1]), "r"(a[2]), "r"(a[3]), "r"(b[0]), "r"(b[1]));
}
__device__ __forceinline__ uint32_t packf(float lo, float hi) {
    uint32_t d;
    asm("cvt.rn.bf16x2.f32 %0, %1, %2;" : "=r"(d) : "f"(hi), "f"(lo));
    return d;
}

// ---------------------------------------------------------------------------
// Elementwise fp32 -> bf16 hi/lo split
// ---------------------------------------------------------------------------
__global__ void cvt_split(const float* __restrict__ in,
                          __nv_bfloat16* __restrict__ h,
                          __nv_bfloat16* __restrict__ l) {
    int i = (blockIdx.x * blockDim.x + threadIdx.x) * 4;
    float4 a = *(const float4*)(in + i);
    float v[4] = {a.x, a.y, a.z, a.w};
    __nv_bfloat16 hh[4], ll[4];
#pragma unroll
    for (int j = 0; j < 4; j++) {
        hh[j] = __float2bfloat16(v[j]);
        ll[j] = __float2bfloat16(v[j] - __bfloat162float(hh[j]));
    }
    *(__nv_bfloat162*)(h + i)     = *(__nv_bfloat162*)&hh[0];
    *(__nv_bfloat162*)(h + i + 2) = *(__nv_bfloat162*)&hh[2];
    *(__nv_bfloat162*)(l + i)     = *(__nv_bfloat162*)&ll[0];
    *(__nv_bfloat162*)(l + i + 2) = *(__nv_bfloat162*)&ll[2];
}

// ---------------------------------------------------------------------------
// W [K][N] fp32 -> W^T hi/lo [N][K] bf16
// ---------------------------------------------------------------------------
__global__ void wt_split(const float* __restrict__ W,
                         __nv_bfloat16* __restrict__ Th,
                         __nv_bfloat16* __restrict__ Tl, int K, int N) {
    __shared__ float t[32][33];
    int n0 = blockIdx.x * 32, k0 = blockIdx.y * 32;
    int tx = threadIdx.x, ty0 = threadIdx.y;
#pragma unroll
    for (int i = 0; i < 4; i++) {
        int ty = ty0 + i * 8;
        t[ty][tx] = W[(size_t)(k0 + ty) * N + n0 + tx];
    }
    __syncthreads();
#pragma unroll
    for (int i = 0; i < 4; i++) {
        int ty = ty0 + i * 8;
        float a = t[tx][ty];
        __nv_bfloat16 h = __float2bfloat16(a);
        __nv_bfloat16 l = __float2bfloat16(a - __bfloat162float(h));
        Th[(size_t)(n0 + ty) * K + k0 + tx] = h;
        Tl[(size_t)(n0 + ty) * K + k0 + tx] = l;
    }
}

// ---------------------------------------------------------------------------
// HMMA bf16x3 GEMM: CTA 128x128, 4 warps (warp tile 64x64), 3-stage cp.async.
// Per k16 step/warp: 16 ldsm4 -> 96 MMA (6:1). K-chunk 32, SW64 smem.
// (R11 version — epilogue MUST stay skinny: fp32 only, no extra params.)
// ---------------------------------------------------------------------------
__global__ __launch_bounds__(128, 2) void gemm_mma(
    const __nv_bfloat16* __restrict__ Ah, const __nv_bfloat16* __restrict__ Al,
    const __nv_bfloat16* __restrict__ Bh, const __nv_bfloat16* __restrict__ Bl,
    float* __restrict__ C, int M, int N, int K) {
    extern __shared__ char smem[];
    const uint32_t sb = smem_u32(smem);   // stage s at sb + s*32768
    const int tid = threadIdx.x, wid = tid >> 5, lane = tid & 31;
    const int m0 = blockIdx.y * 128, n0 = blockIdx.x * 128;
    const int wm0 = (wid >> 1) * 64, wn0 = (wid & 1) * 64;

    const __nv_bfloat16* bA0 = Ah + (size_t)m0 * K;
    const __nv_bfloat16* bA1 = Al + (size_t)m0 * K;
    const __nv_bfloat16* bB0 = Bh + (size_t)n0 * K;
    const __nv_bfloat16* bB1 = Bl + (size_t)n0 * K;

    uint32_t a_r[4], a_z[4];
#pragma unroll
    for (int i = 0; i < 4; i++) {
        int row = wm0 + 16 * i + (lane & 15);
        a_r[i] = row * 64;
        a_z[i] = (row & 6) << 3;
    }
    const uint32_t gA = (lane >> 4) * 16;
    uint32_t b_r[4], b_z[4];
#pragma unroll
    for (int j = 0; j < 4; j++) {
        int row = wn0 + 16 * j + (lane & 7) + ((lane >> 4) << 3);
        b_r[j] = row * 64;
        b_z[j] = (row & 6) << 3;
    }
    const uint32_t gB = ((lane >> 3) & 1) * 16;

    float acc[4][8][4];
#pragma unroll
    for (int i = 0; i < 4; i++)
#pragma unroll
        for (int j = 0; j < 8; j++)
#pragma unroll
            for (int q = 0; q < 4; q++) acc[i][j][q] = 0.f;

#define G_ISSUE(cc, ss)                                                        \
    do {                                                                       \
        const int k0_ = (cc) * 32;                                             \
        const uint32_t stb_ = sb + (ss) * 32768;                               \
        _Pragma("unroll")                                                      \
        for (int i_ = 0; i_ < 16; i_++) {                                      \
            const __nv_bfloat16* base_ =                                       \
                (i_ >> 2) == 0 ? bA0 : (i_ >> 2) == 1 ? bA1                    \
              : (i_ >> 2) == 2 ? bB0 : bB1;                                    \
            int w_ = tid + (i_ & 3) * 128;                                     \
            int r_ = w_ >> 2, c4_ = w_ & 3;                                    \
            cpa16(stb_ + (i_ >> 2) * 8192 + SWZ64(r_ * 64 + c4_ * 16),         \
                  base_ + (size_t)r_ * K + k0_ + c4_ * 8);                     \
        }                                                                      \
        CP_COMMIT();                                                           \
    } while (0)

    const int nch = K / 32;
    G_ISSUE(0, 0);
    G_ISSUE(1, 1);
    int s = 0;
    for (int c = 0; c < nch; c++) {
        if (c + 1 < nch) CP_WAIT1(); else CP_WAIT0();
        __syncthreads();
        if (c + 2 < nch) G_ISSUE(c + 2, (s + 2) % 3);

        const uint32_t stb = sb + s * 32768;
#pragma unroll
        for (int ks = 0; ks < 2; ks++) {
            const uint32_t off = ks * 32;
            uint32_t af[4][4], bh2[4][4], bl2[4][4];
#pragma unroll
            for (int i = 0; i < 4; i++)
                ldsm4(af[i], stb + a_r[i] + ((off + gA) ^ a_z[i]));
#pragma unroll
            for (int j = 0; j < 4; j++) {
                ldsm4(bh2[j], stb + 16384 + b_r[j] + ((off + gB) ^ b_z[j]));
                ldsm4(bl2[j], stb + 24576 + b_r[j] + ((off + gB) ^ b_z[j]));
            }
#pragma unroll
            for (int i = 0; i < 4; i++)
#pragma unroll
                for (int j = 0; j < 4; j++) {
                    mma16816(acc[i][j * 2 + 0], af[i], &bh2[j][0]);
                    mma16816(acc[i][j * 2 + 1], af[i], &bh2[j][2]);
                }
#pragma unroll
            for (int i = 0; i < 4; i++)
#pragma unroll
                for (int j = 0; j < 4; j++) {
                    mma16816(acc[i][j * 2 + 0], af[i], &bl2[j][0]);
                    mma16816(acc[i][j * 2 + 1], af[i], &bl2[j][2]);
                }
#pragma unroll
            for (int i = 0; i < 4; i++)
                ldsm4(af[i], stb + 8192 + a_r[i] + ((off + gA) ^ a_z[i]));
#pragma unroll
            for (int i = 0; i < 4; i++)
#pragma unroll
                for (int j = 0; j < 4; j++) {
                    mma16816(acc[i][j * 2 + 0], af[i], &bh2[j][0]);
                    mma16816(acc[i][j * 2 + 1], af[i], &bh2[j][2]);
                }
        }
        s = (s + 1) % 3;
    }
#undef G_ISSUE

    const int er = lane >> 2, ec = (lane & 3) * 2;
#pragma unroll
    for (int i = 0; i < 4; i++) {
        int r = m0 + wm0 + 16 * i + er;
#pragma unroll
        for (int j = 0; j < 8; j++) {
            int col = n0 + wn0 + 8 * j + ec;
            *(float2*)(C + (size_t)r * N + col)       = make_float2(acc[i][j][0], acc[i][j][1]);
            *(float2*)(C + (size_t)(r + 8) * N + col) = make_float2(acc[i][j][2], acc[i][j][3]);
        }
    }
}

// ---------------------------------------------------------------------------
// RoPE + head split; emit bf16 hi/lo Q(*0.125)/K/V in [BH][T][64]
// ---------------------------------------------------------------------------
__global__ void rope_split(const float* __restrict__ qkv)
{
    int idx = blockIdx.x * blockDim.x + threadIdx.x;
    int d  = idx & (ND - 1);
    int t  = (idx >> 6) & (NT - 1);
    int bh = idx >> 17;
    int b = bh >> 4, h = bh & (NH - 1);
    const float* base = qkv + (size_t)(b * NT + t) * (3 * NC);
    int col  = h * ND + d;
    int colm = h * ND + ((d + ND - 1) & (ND - 1));
    float qd = base[col],      qm = base[colm];
    float kd = base[NC + col], km = base[NC + colm];
    float vd = base[2 * NC + col];

    int fi = d & 31;
    float inv = expf(-(float)fi * (9.210340371976184f / 32.0f));
    float ang = (float)t * inv;
    float sn, cs;
    sincosf(ang, &sn, &cs);

    float qv = (qd * cs + qm * sn) * 0.125f;
    float kv = kd * cs + km * sn;

    __nv_bfloat16 hh;
    hh = __float2bfloat16(qv);
    g_qh[idx] = hh; g_ql[idx] = __float2bfloat16(qv - __bfloat162float(hh));
    hh = __float2bfloat16(kv);
    g_kh[idx] = hh; g_kl[idx] = __float2bfloat16(kv - __bfloat162float(hh));
    hh = __float2bfloat16(vd);
    g_vh[idx] = hh; g_vl[idx] = __float2bfloat16(vd - __bfloat162float(hh));
}

// ---------------------------------------------------------------------------
// Flash attention on HMMA, cp.async double-buffered K/V tiles. LPT order.
// smem: Q hi/lo 32KB @ sb; KV stages 32KB each @ sb+32768 + s*32768.
// ---------------------------------------------------------------------------
__global__ __launch_bounds__(256, 2) void flash_mma(
    const __nv_bfloat16* __restrict__ Qh_, const __nv_bfloat16* __restrict__ Ql_,
    const __nv_bfloat16* __restrict__ Kh_, const __nv_bfloat16* __restrict__ Kl_,
    const __nv_bfloat16* __restrict__ Vh_, const __nv_bfloat16* __restrict__ Vl_,
    __nv_bfloat16* __restrict__ Yh_, __nv_bfloat16* __restrict__ Yl_)
{
    extern __shared__ char smem[];
    const uint32_t sb = smem_u32(smem);
    const uint32_t sQh = sb, sQl = sb + 16384;

    const int bh = blockIdx.y;
    const int qi = (gridDim.x - 1) - blockIdx.x;   // LPT: heaviest first
    const int q0 = qi * 128;
    const int tid = threadIdx.x, wid = tid >> 5, lane = tid & 31;
    const int wm = wid * 16;
    const size_t gbase = (size_t)bh * NT * ND;

    const __nv_bfloat16* pKh = Kh_ + gbase;
    const __nv_bfloat16* pKl = Kl_ + gbase;
    const __nv_bfloat16* pVh = Vh_ + gbase;
    const __nv_bfloat16* pVl = Vl_ + gbase;

    // ---- load Q hi/lo (128x64, SW128) ----
    {
        const __nv_bfloat16* s0 = Qh_ + gbase + (size_t)q0 * ND;
        const __nv_bfloat16* s1 = Ql_ + gbase + (size_t)q0 * ND;
#pragma unroll
        for (int i = 0; i < 4; i++) {
            int idx = tid + i * 256;
            int r = idx >> 3, c8 = idx & 7;
            uint32_t off = SWZ(r * 128 + c8 * 16);
            uint4 v = *(const uint4*)(s0 + (size_t)r * ND + c8 * 8);
            asm volatile("st.shared.v4.b32 [%0], {%1,%2,%3,%4};"
                         :: "r"(sQh + off), "r"(v.x), "r"(v.y), "r"(v.z), "r"(v.w));
            uint4 w = *(const uint4*)(s1 + (size_t)r * ND + c8 * 8);
            asm volatile("st.shared.v4.b32 [%0], {%1,%2,%3,%4};"
                         :: "r"(sQl + off), "r"(w.x), "r"(w.y), "r"(w.z), "r"(w.w));
        }
    }

#define F_ISSUE(kt_, ss)                                                       \
    do {                                                                       \
        const size_t ko_ = (size_t)(kt_) * 64 * ND;                            \
        const uint32_t kvb_ = sb + 32768 + (ss) * 32768;                       \
        _Pragma("unroll")                                                      \
        for (int i_ = 0; i_ < 8; i_++) {                                       \
            const __nv_bfloat16* base_ =                                       \
                (i_ >> 1) == 0 ? pKh : (i_ >> 1) == 1 ? pKl                    \
              : (i_ >> 1) == 2 ? pVh : pVl;                                    \
            int w_ = tid + (i_ & 1) * 256;                                     \
            int r_ = w_ >> 3, c8_ = w_ & 7;                                    \
            cpa16(kvb_ + (i_ >> 1) * 8192 + SWZ(r_ * 128 + c8_ * 16),          \
                  base_ + ko_ + (size_t)r_ * ND + c8_ * 8);                    \
        }                                                                      \
        CP_COMMIT();                                                           \
    } while (0)

    const int rowA = wm + (lane & 15);
    const uint32_t aoff = rowA * 128, aswz = (rowA & 7) * 16;
    const uint32_t gA = (lane >> 4) * 16;
    const int rowB_ = (lane & 7) + ((lane >> 4) << 3);
    const uint32_t bswz = (rowB_ & 7) * 16;
    const uint32_t gB = ((lane >> 3) & 1) * 16;
    const int rowV_ = ((lane >> 3) & 1) * 8 + (lane & 7);
    const uint32_t vswz = (lane & 7) * 16;
    const uint32_t gV = (lane >> 4) * 16;

    float m0 = -1e30f, m1 = -1e30f, l0 = 0.f, l1 = 0.f;
    float oacc[8][4];
#pragma unroll
    for (int j = 0; j < 8; j++)
#pragma unroll
        for (int e = 0; e < 4; e++) oacc[j][e] = 0.f;

    const int nkt = 2 * qi + 2;
    F_ISSUE(0, 0);
    for (int kt = 0; kt < nkt; kt++) {
        const int s = kt & 1;
        if (kt + 1 < nkt) { F_ISSUE(kt + 1, s ^ 1); CP_WAIT1(); }
        else              { CP_WAIT0(); }
        __syncthreads();

        const uint32_t kvb = sb + 32768 + s * 32768;
        const uint32_t sKh = kvb, sKl = kvb + 8192;
        const uint32_t sVh = kvb + 16384, sVl = kvb + 24576;

        if (kt * 64 <= q0 + wm + 15) {
            float sacc[8][4];
#pragma unroll
            for (int j = 0; j < 8; j++)
#pragma unroll
                for (int e = 0; e < 4; e++) sacc[j][e] = 0.f;

#pragma unroll
            for (int ks = 0; ks < 4; ks++) {
                const uint32_t ks32 = ks * 32;
                uint32_t aqh[4], aql[4];
                ldsm4(aqh, sQh + aoff + ((ks32 + gA) ^ aswz));
                ldsm4(aql, sQl + aoff + ((ks32 + gA) ^ aswz));
#pragma unroll
                for (int jb = 0; jb < 4; jb++) {
                    uint32_t roff = (jb * 16 + rowB_) * 128 + ((ks32 + gB) ^ bswz);
                    uint32_t kh4[4], kl4[4];
                    ldsm4(kh4, sKh + roff);
                    ldsm4(kl4, sKl + roff);
                    mma16816(sacc[2 * jb + 0], aqh, &kh4[0]);
                    mma16816(sacc[2 * jb + 1], aqh, &kh4[2]);
                    mma16816(sacc[2 * jb + 0], aqh, &kl4[0]);
                    mma16816(sacc[2 * jb + 1], aqh, &kl4[2]);
                    mma16816(sacc[2 * jb + 0], aql, &kh4[0]);
                    mma16816(sacc[2 * jb + 1], aql, &kh4[2]);
                }
            }

            if ((kt + 1) * 64 - 1 > q0 + wm) {
                const int rb = q0 + wm + (lane >> 2);
                const int cb = kt * 64 + (lane & 3) * 2;
#pragma unroll
                for (int t = 0; t < 8; t++) {
                    int c = cb + t * 8;
                    if (c     > rb)     sacc[t][0] = -1e30f;
                    if (c + 1 > rb)     sacc[t][1] = -1e30f;
                    if (c     > rb + 8) sacc[t][2] = -1e30f;
                    if (c + 1 > rb + 8) sacc[t][3] = -1e30f;
                }
            }

            {
                float mx0 = -1e30f, mx1 = -1e30f;
#pragma unroll
                for (int t = 0; t < 8; t++) {
                    mx0 = fmaxf(mx0, fmaxf(sacc[t][0], sacc[t][1]));
                    mx1 = fmaxf(mx1, fmaxf(sacc[t][2], sacc[t][3]));
                }
                mx0 = fmaxf(mx0, __shfl_xor_sync(0xffffffffu, mx0, 1));
                mx0 = fmaxf(mx0, __shfl_xor_sync(0xffffffffu, mx0, 2));
                mx1 = fmaxf(mx1, __shfl_xor_sync(0xffffffffu, mx1, 1));
                mx1 = fmaxf(mx1, __shfl_xor_sync(0xffffffffu, mx1, 2));
                float mn0 = fmaxf(m0, mx0), mn1 = fmaxf(m1, mx1);
                float a0 = __expf(m0 - mn0), a1 = __expf(m1 - mn1);
                m0 = mn0; m1 = mn1;
                float ls0 = 0.f, ls1 = 0.f;
#pragma unroll
                for (int t = 0; t < 8; t++) {
                    sacc[t][0] = __expf(sacc[t][0] - mn0);
                    sacc[t][1] = __expf(sacc[t][1] - mn0);
                    sacc[t][2] = __expf(sacc[t][2] - mn1);
                    sacc[t][3] = __expf(sacc[t][3] - mn1);
                    ls0 += sacc[t][0] + sacc[t][1];
                    ls1 += sacc[t][2] + sacc[t][3];
                }
                ls0 += __shfl_xor_sync(0xffffffffu, ls0, 1);
                ls0 += __shfl_xor_sync(0xffffffffu, ls0, 2);
                ls1 += __shfl_xor_sync(0xffffffffu, ls1, 1);
                ls1 += __shfl_xor_sync(0xffffffffu, ls1, 2);
                l0 = l0 * a0 + ls0;
                l1 = l1 * a1 + ls1;
#pragma unroll
                for (int j = 0; j < 8; j++) {
                    oacc[j][0] *= a0; oacc[j][1] *= a0;
                    oacc[j][2] *= a1; oacc[j][3] *= a1;
                }
            }

#pragma unroll
            for (int ks = 0; ks < 4; ks++) {
                uint32_t ah[4], al[4];
                ah[0] = packf(sacc[2*ks][0],   sacc[2*ks][1]);
                ah[1] = packf(sacc[2*ks][2],   sacc[2*ks][3]);
                ah[2] = packf(sacc[2*ks+1][0], sacc[2*ks+1][1]);
                ah[3] = packf(sacc[2*ks+1][2], sacc[2*ks+1][3]);
#pragma unroll
                for (int r = 0; r < 4; r++) {
                    float flo = __uint_as_float(ah[r] << 16);
                    float fhi = __uint_as_float(ah[r] & 0xffff0000u);
                    float s0 = sacc[2*ks + (r >> 1)][(r & 1) * 2 + 0];
                    float s1 = sacc[2*ks + (r >> 1)][(r & 1) * 2 + 1];
                    al[r] = packf(s0 - flo, s1 - fhi);
                }
                const uint32_t vrow = (ks * 16 + rowV_) * 128;
#pragma unroll
                for (int jb = 0; jb < 4; jb++) {
                    uint32_t voff = vrow + ((jb * 32 + gV) ^ vswz);
                    uint32_t vh4[4], vl4[4];
                    ldsm4t(vh4, sVh + voff);
                    ldsm4t(vl4, sVl + voff);
                    mma16816(oacc[2 * jb + 0], ah, &vh4[0]);
                    mma16816(oacc[2 * jb + 1], ah, &vh4[2]);
                    mma16816(oacc[2 * jb + 0], ah, &vl4[0]);
                    mma16816(oacc[2 * jb + 1], ah, &vl4[2]);
                    mma16816(oacc[2 * jb + 0], al, &vh4[0]);
                    mma16816(oacc[2 * jb + 1], al, &vh4[2]);
                }
            }
        }
        __syncthreads();
    }
#undef F_ISSUE

    {
        const int b = bh >> 4, h = bh & (NH - 1);
        const float i0 = 1.f / l0, i1 = 1.f / l1;
        const int t0 = q0 + wm + (lane >> 2);
        const int c0 = h * ND + (lane & 3) * 2;
#pragma unroll
        for (int j = 0; j < 8; j++) {
            float v0 = oacc[j][0] * i0, v1 = oacc[j][1] * i0;
            float v2 = oacc[j][2] * i1, v3 = oacc[j][3] * i1;
            uint32_t ph0 = packf(v0, v1), ph1 = packf(v2, v3);
            uint32_t pl0 = packf(v0 - __uint_as_float(ph0 << 16),
                                 v1 - __uint_as_float(ph0 & 0xffff0000u));
            uint32_t pl1 = packf(v2 - __uint_as_float(ph1 << 16),
                                 v3 - __uint_as_float(ph1 & 0xffff0000u));
            size_t o0 = (size_t)(b * NT + t0) * NC + c0 + j * 8;
            size_t o1 = (size_t)(b * NT + t0 + 8) * NC + c0 + j * 8;
            *(uint32_t*)(Yh_ + o0) = ph0;
            *(uint32_t*)(Yl_ + o0) = pl0;
            *(uint32_t*)(Yh_ + o1) = ph1;
            *(uint32_t*)(Yl_ + o1) = pl1;
        }
    }
}

// ---------------------------------------------------------------------------
extern "C" void kernel_launch(void* const* d_in, const int* in_sizes, int n_in,
                              void* d_out, int out_size)
{
    const float* x  = (const float*)d_in[0];
    const float* Wa = (const float*)d_in[1];
    const float* Wp = (const float*)d_in[2];
    float* out = (float*)d_out;

    float* qkv;
    __nv_bfloat16 *xh, *xl, *yh, *yl, *wah, *wal, *wph, *wpl;
    __nv_bfloat16 *qh, *ql, *kh, *kl, *vh, *vl;
    cudaGetSymbolAddress((void**)&qkv, g_qkv);
    cudaGetSymbolAddress((void**)&xh,  g_xh);
    cudaGetSymbolAddress((void**)&xl,  g_xl);
    cudaGetSymbolAddress((void**)&yh,  g_yh);
    cudaGetSymbolAddress((void**)&yl,  g_yl);
    cudaGetSymbolAddress((void**)&wah, g_wah);
    cudaGetSymbolAddress((void**)&wal, g_wal);
    cudaGetSymbolAddress((void**)&wph, g_wph);
    cudaGetSymbolAddress((void**)&wpl, g_wpl);
    cudaGetSymbolAddress((void**)&qh,  g_qh);
    cudaGetSymbolAddress((void**)&ql,  g_ql);
    cudaGetSymbolAddress((void**)&kh,  g_kh);
    cudaGetSymbolAddress((void**)&kl,  g_kl);
    cudaGetSymbolAddress((void**)&vh,  g_vh);
    cudaGetSymbolAddress((void**)&vl,  g_vl);

    const int gemm_smem = 98304;          // 3 stages x 32KB
    cudaFuncSetAttribute(gemm_mma, cudaFuncAttributeMaxDynamicSharedMemorySize, gemm_smem);
    const int flash_smem = 98304;         // Q 32KB + 2 stages x 32KB
    cudaFuncSetAttribute(flash_mma, cudaFuncAttributeMaxDynamicSharedMemorySize, flash_smem);

    // 0) input splits / weight transposes
    cvt_split<<<(NM * NC) / 1024, 256>>>(x, xh, xl);
    wt_split<<<dim3(3 * NC / 32, NC / 32), dim3(32, 8)>>>(Wa, wah, wal, NC, 3 * NC);
    wt_split<<<dim3(NC / 32, NC / 32), dim3(32, 8)>>>(Wp, wph, wpl, NC, NC);

    // 1) QKV = x @ W_attn
    gemm_mma<<<dim3(3 * NC / 128, NM / 128), 128, gemm_smem>>>(
        xh, xl, wah, wal, qkv, NM, 3 * NC, NC);

    // 2) RoPE + split to bf16 hi/lo heads
    rope_split<<<(NBH * NT * ND) / 256, 256>>>(qkv);

    // 3) Flash attention (causal) on tensor cores -> yh/yl
    flash_mma<<<dim3(NT / 128, NBH), 256, flash_smem>>>(
        qh, ql, kh, kl, vh, vl, yh, yl);

    // 4) out = y @ W_proj
    gemm_mma<<<dim3(NC / 128, NM / 128), 128, gemm_smem>>>(
        yh, yl, wph, wpl, out, NM, NC, NC);
}

// round 15
// speedup vs baseline: 1.5727x; 1.0083x over previous
#include <cuda_runtime.h>
#include <cuda_bf16.h>
#include <math.h>
#include <stdint.h>

#define NB 2
#define NT 2048
#define NC 1024
#define NH 16
#define ND 64
#define NBH (NB*NH)
#define NM (NB*NT)   // 4096 rows

// ---------------------------------------------------------------------------
// Scratch (static device allocations)
// ---------------------------------------------------------------------------
__device__ float g_qkv[(size_t)NM * 3 * NC];            // [4096, 3072]

__device__ __nv_bfloat16 g_xh[(size_t)NM * NC];         // x hi/lo
__device__ __nv_bfloat16 g_xl[(size_t)NM * NC];
__device__ __nv_bfloat16 g_yh[(size_t)NM * NC];         // attn out hi/lo
__device__ __nv_bfloat16 g_yl[(size_t)NM * NC];
__device__ __nv_bfloat16 g_wah[(size_t)(3*NC) * NC];    // Wa^T hi/lo [3072][1024]
__device__ __nv_bfloat16 g_wal[(size_t)(3*NC) * NC];
__device__ __nv_bfloat16 g_wph[(size_t)NC * NC];        // Wp^T hi/lo
__device__ __nv_bfloat16 g_wpl[(size_t)NC * NC];

__device__ __nv_bfloat16 g_qh[(size_t)NBH * NT * ND];   // RoPE'd Q*scale hi/lo
__device__ __nv_bfloat16 g_ql[(size_t)NBH * NT * ND];
__device__ __nv_bfloat16 g_kh[(size_t)NBH * NT * ND];
__device__ __nv_bfloat16 g_kl[(size_t)NBH * NT * ND];
__device__ __nv_bfloat16 g_vh[(size_t)NBH * NT * ND];
__device__ __nv_bfloat16 g_vl[(size_t)NBH * NT * ND];

__device__ float g_cs[(size_t)NT * ND * 2];             // (cos,sin) per (t,d)

// ---------------------------------------------------------------------------
__device__ __forceinline__ uint32_t smem_u32(const void* p) {
    uint32_t a;
    asm("{ .reg .u64 t; cvta.to.shared.u64 t, %1; cvt.u32.u64 %0, t; }"
        : "=r"(a) : "l"(p));
    return a;
}
#define SWZ(o)   ((o) ^ (((o) >> 3) & 0x70))   // SW128 (128B rows)
#define SWZ64(o) ((o) ^ (((o) >> 3) & 0x30))   // SW64  (64B rows)

__device__ __forceinline__ void cpa16(uint32_t dst, const void* src) {
    asm volatile("cp.async.cg.shared.global [%0], [%1], 16;"
                 :: "r"(dst), "l"(src) : "memory");
}
#define CP_COMMIT() asm volatile("cp.async.commit_group;" ::: "memory")
#define CP_WAIT1()  asm volatile("cp.async.wait_group 1;" ::: "memory")
#define CP_WAIT0()  asm volatile("cp.async.wait_group 0;" ::: "memory")

__device__ __forceinline__ void ldsm4(uint32_t* r, uint32_t addr) {
    asm volatile("ldmatrix.sync.aligned.m8n8.x4.shared.b16 {%0,%1,%2,%3}, [%4];"
                 : "=r"(r[0]), "=r"(r[1]), "=r"(r[2]), "=r"(r[3]) : "r"(addr));
}
__device__ __forceinline__ void ldsm4t(uint32_t* r, uint32_t addr) {
    asm volatile("ldmatrix.sync.aligned.m8n8.x4.trans.shared.b16 {%0,%1,%2,%3}, [%4];"
                 : "=r"(r[0]), "=r"(r[1]), "=r"(r[2]), "=r"(r[3]) : "r"(addr));
}
__device__ __forceinline__ void mma16816(float* d, const uint32_t* a, const uint32_t* b) {
    asm volatile(
        "mma.sync.aligned.m16n8k16.row.col.f32.bf16.bf16.f32 "
        "{%0,%1,%2,%3}, {%4,%5,%6,%7}, {%8,%9}, {%0,%1,%2,%3};"
        : "+f"(d[0]), "+f"(d[1]), "+f"(d[2]), "+f"(d[3])
        : "r"(a[0]), "r"(a[1]), "r"(a[2]), "r"(a[3]), "r"(b[0]), "r"(b[1]));
}
__device__ __forceinline__ uint32_t packf(float lo, float hi) {
    uint32_t d;
    asm("cvt.rn.bf16x2.f32 %0, %1, %2;" : "=r"(d) : "f"(hi), "f"(lo));
    return d;
}

// ---------------------------------------------------------------------------
// cos/sin table: g_cs[t][d] = {cos(t*f(d)), sin(t*f(d))}, freq dup over 32
// ---------------------------------------------------------------------------
__global__ void cs_init() {
    int idx = blockIdx.x * blockDim.x + threadIdx.x;   // over 2048*64
    int t = idx >> 6, d = idx & 63;
    int fi = d & 31;
    float inv = expf(-(float)fi * (9.210340371976184f / 32.0f));
    float sn, cs;
    sincosf((float)t * inv, &sn, &cs);
    g_cs[idx * 2 + 0] = cs;
    g_cs[idx * 2 + 1] = sn;
}

// ---------------------------------------------------------------------------
// Elementwise fp32 -> bf16 hi/lo split
// ---------------------------------------------------------------------------
__global__ void cvt_split(const float* __restrict__ in,
                          __nv_bfloat16* __restrict__ h,
                          __nv_bfloat16* __restrict__ l) {
    int i = (blockIdx.x * blockDim.x + threadIdx.x) * 4;
    float4 a = *(const float4*)(in + i);
    float v[4] = {a.x, a.y, a.z, a.w};
    __nv_bfloat16 hh[4], ll[4];
#pragma unroll
    for (int j = 0; j < 4; j++) {
        hh[j] = __float2bfloat16(v[j]);
        ll[j] = __float2bfloat16(v[j] - __bfloat162float(hh[j]));
    }
    *(__nv_bfloat162*)(h + i)     = *(__nv_bfloat162*)&hh[0];
    *(__nv_bfloat162*)(h + i + 2) = *(__nv_bfloat162*)&hh[2];
    *(__nv_bfloat162*)(l + i)     = *(__nv_bfloat162*)&ll[0];
    *(__nv_bfloat162*)(l + i + 2) = *(__nv_bfloat162*)&ll[2];
}

// ---------------------------------------------------------------------------
// W [K][N] fp32 -> W^T hi/lo [N][K] bf16
// ---------------------------------------------------------------------------
__global__ void wt_split(const float* __restrict__ W,
                         __nv_bfloat16* __restrict__ Th,
                         __nv_bfloat16* __restrict__ Tl, int K, int N) {
    __shared__ float t[32][33];
    int n0 = blockIdx.x * 32, k0 = blockIdx.y * 32;
    int tx = threadIdx.x, ty0 = threadIdx.y;
#pragma unroll
    for (int i = 0; i < 4; i++) {
        int ty = ty0 + i * 8;
        t[ty][tx] = W[(size_t)(k0 + ty) * N + n0 + tx];
    }
    __syncthreads();
#pragma unroll
    for (int i = 0; i < 4; i++) {
        int ty = ty0 + i * 8;
        float a = t[tx][ty];
        __nv_bfloat16 h = __float2bfloat16(a);
        __nv_bfloat16 l = __float2bfloat16(a - __bfloat162float(h));
        Th[(size_t)(n0 + ty) * K + k0 + tx] = h;
        Tl[(size_t)(n0 + ty) * K + k0 + tx] = l;
    }
}

// ---------------------------------------------------------------------------
// HMMA bf16x3 GEMM: CTA 128x128, 4 warps (warp tile 64x64), 3-stage cp.async.
// (R11 version — epilogue MUST stay skinny: fp32 only, no extra params.)
// ---------------------------------------------------------------------------
__global__ __launch_bounds__(128, 2) void gemm_mma(
    const __nv_bfloat16* __restrict__ Ah, const __nv_bfloat16* __restrict__ Al,
    const __nv_bfloat16* __restrict__ Bh, const __nv_bfloat16* __restrict__ Bl,
    float* __restrict__ C, int M, int N, int K) {
    extern __shared__ char smem[];
    const uint32_t sb = smem_u32(smem);   // stage s at sb + s*32768
    const int tid = threadIdx.x, wid = tid >> 5, lane = tid & 31;
    const int m0 = blockIdx.y * 128, n0 = blockIdx.x * 128;
    const int wm0 = (wid >> 1) * 64, wn0 = (wid & 1) * 64;

    const __nv_bfloat16* bA0 = Ah + (size_t)m0 * K;
    const __nv_bfloat16* bA1 = Al + (size_t)m0 * K;
    const __nv_bfloat16* bB0 = Bh + (size_t)n0 * K;
    const __nv_bfloat16* bB1 = Bl + (size_t)n0 * K;

    uint32_t a_r[4], a_z[4];
#pragma unroll
    for (int i = 0; i < 4; i++) {
        int row = wm0 + 16 * i + (lane & 15);
        a_r[i] = row * 64;
        a_z[i] = (row & 6) << 3;
    }
    const uint32_t gA = (lane >> 4) * 16;
    uint32_t b_r[4], b_z[4];
#pragma unroll
    for (int j = 0; j < 4; j++) {
        int row = wn0 + 16 * j + (lane & 7) + ((lane >> 4) << 3);
        b_r[j] = row * 64;
        b_z[j] = (row & 6) << 3;
    }
    const uint32_t gB = ((lane >> 3) & 1) * 16;

    float acc[4][8][4];
#pragma unroll
    for (int i = 0; i < 4; i++)
#pragma unroll
        for (int j = 0; j < 8; j++)
#pragma unroll
            for (int q = 0; q < 4; q++) acc[i][j][q] = 0.f;

#define G_ISSUE(cc, ss)                                                        \
    do {                                                                       \
        const int k0_ = (cc) * 32;                                             \
        const uint32_t stb_ = sb + (ss) * 32768;                               \
        _Pragma("unroll")                                                      \
        for (int i_ = 0; i_ < 16; i_++) {                                      \
            const __nv_bfloat16* base_ =                                       \
                (i_ >> 2) == 0 ? bA0 : (i_ >> 2) == 1 ? bA1                    \
              : (i_ >> 2) == 2 ? bB0 : bB1;                                    \
            int w_ = tid + (i_ & 3) * 128;                                     \
            int r_ = w_ >> 2, c4_ = w_ & 3;                                    \
            cpa16(stb_ + (i_ >> 2) * 8192 + SWZ64(r_ * 64 + c4_ * 16),         \
                  base_ + (size_t)r_ * K + k0_ + c4_ * 8);                     \
        }                                                                      \
        CP_COMMIT();                                                           \
    } while (0)

    const int nch = K / 32;
    G_ISSUE(0, 0);
    G_ISSUE(1, 1);
    int s = 0;
    for (int c = 0; c < nch; c++) {
        if (c + 1 < nch) CP_WAIT1(); else CP_WAIT0();
        __syncthreads();
        if (c + 2 < nch) G_ISSUE(c + 2, (s + 2) % 3);

        const uint32_t stb = sb + s * 32768;
#pragma unroll
        for (int ks = 0; ks < 2; ks++) {
            const uint32_t off = ks * 32;
            uint32_t af[4][4], bh2[4][4], bl2[4][4];
#pragma unroll
            for (int i = 0; i < 4; i++)
                ldsm4(af[i], stb + a_r[i] + ((off + gA) ^ a_z[i]));
#pragma unroll
            for (int j = 0; j < 4; j++) {
                ldsm4(bh2[j], stb + 16384 + b_r[j] + ((off + gB) ^ b_z[j]));
                ldsm4(bl2[j], stb + 24576 + b_r[j] + ((off + gB) ^ b_z[j]));
            }
#pragma unroll
            for (int i = 0; i < 4; i++)
#pragma unroll
                for (int j = 0; j < 4; j++) {
                    mma16816(acc[i][j * 2 + 0], af[i], &bh2[j][0]);
                    mma16816(acc[i][j * 2 + 1], af[i], &bh2[j][2]);
                }
#pragma unroll
            for (int i = 0; i < 4; i++)
#pragma unroll
                for (int j = 0; j < 4; j++) {
                    mma16816(acc[i][j * 2 + 0], af[i], &bl2[j][0]);
                    mma16816(acc[i][j * 2 + 1], af[i], &bl2[j][2]);
                }
#pragma unroll
            for (int i = 0; i < 4; i++)
                ldsm4(af[i], stb + 8192 + a_r[i] + ((off + gA) ^ a_z[i]));
#pragma unroll
            for (int i = 0; i < 4; i++)
#pragma unroll
                for (int j = 0; j < 4; j++) {
                    mma16816(acc[i][j * 2 + 0], af[i], &bh2[j][0]);
                    mma16816(acc[i][j * 2 + 1], af[i], &bh2[j][2]);
                }
        }
        s = (s + 1) % 3;
    }
#undef G_ISSUE

    const int er = lane >> 2, ec = (lane & 3) * 2;
#pragma unroll
    for (int i = 0; i < 4; i++) {
        int r = m0 + wm0 + 16 * i + er;
#pragma unroll
        for (int j = 0; j < 8; j++) {
            int col = n0 + wn0 + 8 * j + ec;
            *(float2*)(C + (size_t)r * N + col)       = make_float2(acc[i][j][0], acc[i][j][1]);
            *(float2*)(C + (size_t)(r + 8) * N + col) = make_float2(acc[i][j][2], acc[i][j][3]);
        }
    }
}

// ---------------------------------------------------------------------------
// RoPE + head split, table-driven, 2 elements per thread.
// q_out[d] = q[d]*cos + q[(d-1)%64]*sin ; Q also scaled by 0.125.
// ---------------------------------------------------------------------------
__global__ void rope_split(const float* __restrict__ qkv)
{
    int idx = blockIdx.x * blockDim.x + threadIdx.x;  // over BH*T*32
    int p  = idx & 31;
    int t  = (idx >> 5) & (NT - 1);
    int bh = idx >> 16;
    int b = bh >> 4, h = bh & (NH - 1);
    int d0 = p * 2;
    int dmo = (d0 + 63) & 63;          // d0 - 1 (odd index, scalar load)
    const float* base = qkv + (size_t)(b * NT + t) * (3 * NC);
    int cq = h * ND;

    float2 q2 = *(const float2*)(base + cq + d0);
    float  qm = base[cq + dmo];
    float2 k2 = *(const float2*)(base + NC + cq + d0);
    float  km = base[NC + cq + dmo];
    float2 v2 = *(const float2*)(base + 2 * NC + cq + d0);

    float4 cs2 = *(const float4*)(g_cs + ((size_t)t * ND + d0) * 2); // c0,s0,c1,s1

    float rq0 = (q2.x * cs2.x + qm   * cs2.y) * 0.125f;
    float rq1 = (q2.y * cs2.z + q2.x * cs2.w) * 0.125f;
    float rk0 = k2.x * cs2.x + km   * cs2.y;
    float rk1 = k2.y * cs2.z + k2.x * cs2.w;

    size_t o = ((size_t)bh * NT + t) * ND + d0;
    uint32_t ph, pl;
    ph = packf(rq0, rq1);
    pl = packf(rq0 - __uint_as_float(ph << 16), rq1 - __uint_as_float(ph & 0xffff0000u));
    *(uint32_t*)(g_qh + o) = ph;
    *(uint32_t*)(g_ql + o) = pl;
    ph = packf(rk0, rk1);
    pl = packf(rk0 - __uint_as_float(ph << 16), rk1 - __uint_as_float(ph & 0xffff0000u));
    *(uint32_t*)(g_kh + o) = ph;
    *(uint32_t*)(g_kl + o) = pl;
    ph = packf(v2.x, v2.y);
    pl = packf(v2.x - __uint_as_float(ph << 16), v2.y - __uint_as_float(ph & 0xffff0000u));
    *(uint32_t*)(g_vh + o) = ph;
    *(uint32_t*)(g_vl + o) = pl;
}

// ---------------------------------------------------------------------------
// Flash attention on HMMA, cp.async double-buffered K/V tiles. LPT order.
// smem: Q hi/lo 32KB @ sb; KV stages 32KB each @ sb+32768 + s*32768.
// ---------------------------------------------------------------------------
__global__ __launch_bounds__(256, 2) void flash_mma(
    const __nv_bfloat16* __restrict__ Qh_, const __nv_bfloat16* __restrict__ Ql_,
    const __nv_bfloat16* __restrict__ Kh_, const __nv_bfloat16* __restrict__ Kl_,
    const __nv_bfloat16* __restrict__ Vh_, const __nv_bfloat16* __restrict__ Vl_,
    __nv_bfloat16* __restrict__ Yh_, __nv_bfloat16* __restrict__ Yl_)
{
    extern __shared__ char smem[];
    const uint32_t sb = smem_u32(smem);
    const uint32_t sQh = sb, sQl = sb + 16384;

    const int bh = blockIdx.y;
    const int qi = (gridDim.x - 1) - blockIdx.x;   // LPT: heaviest first
    const int q0 = qi * 128;
    const int tid = threadIdx.x, wid = tid >> 5, lane = tid & 31;
    const int wm = wid * 16;
    const size_t gbase = (size_t)bh * NT * ND;

    const __nv_bfloat16* pKh = Kh_ + gbase;
    const __nv_bfloat16* pKl = Kl_ + gbase;
    const __nv_bfloat16* pVh = Vh_ + gbase;
    const __nv_bfloat16* pVl = Vl_ + gbase;

    // ---- load Q hi/lo (128x64, SW128) ----
    {
        const __nv_bfloat16* s0 = Qh_ + gbase + (size_t)q0 * ND;
        const __nv_bfloat16* s1 = Ql_ + gbase + (size_t)q0 * ND;
#pragma unroll
        for (int i = 0; i < 4; i++) {
            int idx = tid + i * 256;
            int r = idx >> 3, c8 = idx & 7;
            uint32_t off = SWZ(r * 128 + c8 * 16);
            uint4 v = *(const uint4*)(s0 + (size_t)r * ND + c8 * 8);
            asm volatile("st.shared.v4.b32 [%0], {%1,%2,%3,%4};"
                         :: "r"(sQh + off), "r"(v.x), "r"(v.y), "r"(v.z), "r"(v.w));
            uint4 w = *(const uint4*)(s1 + (size_t)r * ND + c8 * 8);
            asm volatile("st.shared.v4.b32 [%0], {%1,%2,%3,%4};"
                         :: "r"(sQl + off), "r"(w.x), "r"(w.y), "r"(w.z), "r"(w.w));
        }
    }

#define F_ISSUE(kt_, ss)                                                       \
    do {                                                                       \
        const size_t ko_ = (size_t)(kt_) * 64 * ND;                            \
        const uint32_t kvb_ = sb + 32768 + (ss) * 32768;                       \
        _Pragma("unroll")                                                      \
        for (int i_ = 0; i_ < 8; i_++) {                                       \
            const __nv_bfloat16* base_ =                                       \
                (i_ >> 1) == 0 ? pKh : (i_ >> 1) == 1 ? pKl                    \
              : (i_ >> 1) == 2 ? pVh : pVl;                                    \
            int w_ = tid + (i_ & 1) * 256;                                     \
            int r_ = w_ >> 3, c8_ = w_ & 7;                                    \
            cpa16(kvb_ + (i_ >> 1) * 8192 + SWZ(r_ * 128 + c8_ * 16),          \
                  base_ + ko_ + (size_t)r_ * ND + c8_ * 8);                    \
        }                                                                      \
        CP_COMMIT();                                                           \
    } while (0)

    const int rowA = wm + (lane & 15);
    const uint32_t aoff = rowA * 128, aswz = (rowA & 7) * 16;
    const uint32_t gA = (lane >> 4) * 16;
    const int rowB_ = (lane & 7) + ((lane >> 4) << 3);
    const uint32_t bswz = (rowB_ & 7) * 16;
    const uint32_t gB = ((lane >> 3) & 1) * 16;
    const int rowV_ = ((lane >> 3) & 1) * 8 + (lane & 7);
    const uint32_t vswz = (lane & 7) * 16;
    const uint32_t gV = (lane >> 4) * 16;

    float m0 = -1e30f, m1 = -1e30f, l0 = 0.f, l1 = 0.f;
    float oacc[8][4];
#pragma unroll
    for (int j = 0; j < 8; j++)
#pragma unroll
        for (int e = 0; e < 4; e++) oacc[j][e] = 0.f;

    const int nkt = 2 * qi + 2;
    F_ISSUE(0, 0);
    for (int kt = 0; kt < nkt; kt++) {
        const int s = kt & 1;
        if (kt + 1 < nkt) { F_ISSUE(kt + 1, s ^ 1); CP_WAIT1(); }
        else              { CP_WAIT0(); }
        __syncthreads();

        const uint32_t kvb = sb + 32768 + s * 32768;
        const uint32_t sKh = kvb, sKl = kvb + 8192;
        const uint32_t sVh = kvb + 16384, sVl = kvb + 24576;

        if (kt * 64 <= q0 + wm + 15) {
            float sacc[8][4];
#pragma unroll
            for (int j = 0; j < 8; j++)
#pragma unroll
                for (int e = 0; e < 4; e++) sacc[j][e] = 0.f;

#pragma unroll
            for (int ks = 0; ks < 4; ks++) {
                const uint32_t ks32 = ks * 32;
                uint32_t aqh[4], aql[4];
                ldsm4(aqh, sQh + aoff + ((ks32 + gA) ^ aswz));
                ldsm4(aql, sQl + aoff + ((ks32 + gA) ^ aswz));
#pragma unroll
                for (int jb = 0; jb < 4; jb++) {
                    uint32_t roff = (jb * 16 + rowB_) * 128 + ((ks32 + gB) ^ bswz);
                    uint32_t kh4[4], kl4[4];
                    ldsm4(kh4, sKh + roff);
                    ldsm4(kl4, sKl + roff);
                    mma16816(sacc[2 * jb + 0], aqh, &kh4[0]);
                    mma16816(sacc[2 * jb + 1], aqh, &kh4[2]);
                    mma16816(sacc[2 * jb + 0], aqh, &kl4[0]);
                    mma16816(sacc[2 * jb + 1], aqh, &kl4[2]);
                    mma16816(sacc[2 * jb + 0], aql, &kh4[0]);
                    mma16816(sacc[2 * jb + 1], aql, &kh4[2]);
                }
            }

            if ((kt + 1) * 64 - 1 > q0 + wm) {
                const int rb = q0 + wm + (lane >> 2);
                const int cb = kt * 64 + (lane & 3) * 2;
#pragma unroll
                for (int t = 0; t < 8; t++) {
                    int c = cb + t * 8;
                    if (c     > rb)     sacc[t][0] = -1e30f;
                    if (c + 1 > rb)     sacc[t][1] = -1e30f;
                    if (c     > rb + 8) sacc[t][2] = -1e30f;
                    if (c + 1 > rb + 8) sacc[t][3] = -1e30f;
                }
            }

            {
                float mx0 = -1e30f, mx1 = -1e30f;
#pragma unroll
                for (int t = 0; t < 8; t++) {
                    mx0 = fmaxf(mx0, fmaxf(sacc[t][0], sacc[t][1]));
                    mx1 = fmaxf(mx1, fmaxf(sacc[t][2], sacc[t][3]));
                }
                mx0 = fmaxf(mx0, __shfl_xor_sync(0xffffffffu, mx0, 1));
                mx0 = fmaxf(mx0, __shfl_xor_sync(0xffffffffu, mx0, 2));
                mx1 = fmaxf(mx1, __shfl_xor_sync(0xffffffffu, mx1, 1));
                mx1 = fmaxf(mx1, __shfl_xor_sync(0xffffffffu, mx1, 2));
                float mn0 = fmaxf(m0, mx0), mn1 = fmaxf(m1, mx1);
                float a0 = __expf(m0 - mn0), a1 = __expf(m1 - mn1);
                m0 = mn0; m1 = mn1;
                float ls0 = 0.f, ls1 = 0.f;
#pragma unroll
                for (int t = 0; t < 8; t++) {
                    sacc[t][0] = __expf(sacc[t][0] - mn0);
                    sacc[t][1] = __expf(sacc[t][1] - mn0);
                    sacc[t][2] = __expf(sacc[t][2] - mn1);
                    sacc[t][3] = __expf(sacc[t][3] - mn1);
                    ls0 += sacc[t][0] + sacc[t][1];
                    ls1 += sacc[t][2] + sacc[t][3];
                }
                ls0 += __shfl_xor_sync(0xffffffffu, ls0, 1);
                ls0 += __shfl_xor_sync(0xffffffffu, ls0, 2);
                ls1 += __shfl_xor_sync(0xffffffffu, ls1, 1);
                ls1 += __shfl_xor_sync(0xffffffffu, ls1, 2);
                l0 = l0 * a0 + ls0;
                l1 = l1 * a1 + ls1;
#pragma unroll
                for (int j = 0; j < 8; j++) {
                    oacc[j][0] *= a0; oacc[j][1] *= a0;
                    oacc[j][2] *= a1; oacc[j][3] *= a1;
                }
            }

#pragma unroll
            for (int ks = 0; ks < 4; ks++) {
                uint32_t ah[4], al[4];
                ah[0] = packf(sacc[2*ks][0],   sacc[2*ks][1]);
                ah[1] = packf(sacc[2*ks][2],   sacc[2*ks][3]);
                ah[2] = packf(sacc[2*ks+1][0], sacc[2*ks+1][1]);
                ah[3] = packf(sacc[2*ks+1][2], sacc[2*ks+1][3]);
#pragma unroll
                for (int r = 0; r < 4; r++) {
                    float flo = __uint_as_float(ah[r] << 16);
                    float fhi = __uint_as_float(ah[r] & 0xffff0000u);
                    float s0 = sacc[2*ks + (r >> 1)][(r & 1) * 2 + 0];
                    float s1 = sacc[2*ks + (r >> 1)][(r & 1) * 2 + 1];
                    al[r] = packf(s0 - flo, s1 - fhi);
                }
                const uint32_t vrow = (ks * 16 + rowV_) * 128;
#pragma unroll
                for (int jb = 0; jb < 4; jb++) {
                    uint32_t voff = vrow + ((jb * 32 + gV) ^ vswz);
                    uint32_t vh4[4], vl4[4];
                    ldsm4t(vh4, sVh + voff);
                    ldsm4t(vl4, sVl + voff);
                    mma16816(oacc[2 * jb + 0], ah, &vh4[0]);
                    mma16816(oacc[2 * jb + 1], ah, &vh4[2]);
                    mma16816(oacc[2 * jb + 0], ah, &vl4[0]);
                    mma16816(oacc[2 * jb + 1], ah, &vl4[2]);
                    mma16816(oacc[2 * jb + 0], al, &vh4[0]);
                    mma16816(oacc[2 * jb + 1], al, &vh4[2]);
                }
            }
        }
        __syncthreads();
    }
#undef F_ISSUE

    {
        const int b = bh >> 4, h = bh & (NH - 1);
        const float i0 = 1.f / l0, i1 = 1.f / l1;
        const int t0 = q0 + wm + (lane >> 2);
        const int c0 = h * ND + (lane & 3) * 2;
#pragma unroll
        for (int j = 0; j < 8; j++) {
            float v0 = oacc[j][0] * i0, v1 = oacc[j][1] * i0;
            float v2 = oacc[j][2] * i1, v3 = oacc[j][3] * i1;
            uint32_t ph0 = packf(v0, v1), ph1 = packf(v2, v3);
            uint32_t pl0 = packf(v0 - __uint_as_float(ph0 << 16),
                                 v1 - __uint_as_float(ph0 & 0xffff0000u));
            uint32_t pl1 = packf(v2 - __uint_as_float(ph1 << 16),
                                 v3 - __uint_as_float(ph1 & 0xffff0000u));
            size_t o0 = (size_t)(b * NT + t0) * NC + c0 + j * 8;
            size_t o1 = (size_t)(b * NT + t0 + 8) * NC + c0 + j * 8;
            *(uint32_t*)(Yh_ + o0) = ph0;
            *(uint32_t*)(Yl_ + o0) = pl0;
            *(uint32_t*)(Yh_ + o1) = ph1;
            *(uint32_t*)(Yl_ + o1) = pl1;
        }
    }
}

// ---------------------------------------------------------------------------
extern "C" void kernel_launch(void* const* d_in, const int* in_sizes, int n_in,
                              void* d_out, int out_size)
{
    const float* x  = (const float*)d_in[0];
    const float* Wa = (const float*)d_in[1];
    const float* Wp = (const float*)d_in[2];
    float* out = (float*)d_out;

    float* qkv;
    __nv_bfloat16 *xh, *xl, *yh, *yl, *wah, *wal, *wph, *wpl;
    __nv_bfloat16 *qh, *ql, *kh, *kl, *vh, *vl;
    cudaGetSymbolAddress((void**)&qkv, g_qkv);
    cudaGetSymbolAddress((void**)&xh,  g_xh);
    cudaGetSymbolAddress((void**)&xl,  g_xl);
    cudaGetSymbolAddress((void**)&yh,  g_yh);
    cudaGetSymbolAddress((void**)&yl,  g_yl);
    cudaGetSymbolAddress((void**)&wah, g_wah);
    cudaGetSymbolAddress((void**)&wal, g_wal);
    cudaGetSymbolAddress((void**)&wph, g_wph);
    cudaGetSymbolAddress((void**)&wpl, g_wpl);
    cudaGetSymbolAddress((void**)&qh,  g_qh);
    cudaGetSymbolAddress((void**)&ql,  g_ql);
    cudaGetSymbolAddress((void**)&kh,  g_kh);
    cudaGetSymbolAddress((void**)&kl,  g_kl);
    cudaGetSymbolAddress((void**)&vh,  g_vh);
    cudaGetSymbolAddress((void**)&vl,  g_vl);

    const int gemm_smem = 98304;          // 3 stages x 32KB
    cudaFuncSetAttribute(gemm_mma, cudaFuncAttributeMaxDynamicSharedMemorySize, gemm_smem);
    const int flash_smem = 98304;         // Q 32KB + 2 stages x 32KB
    cudaFuncSetAttribute(flash_mma, cudaFuncAttributeMaxDynamicSharedMemorySize, flash_smem);

    // 0) cos/sin table, input splits, weight transposes
    cs_init<<<(NT * ND) / 256, 256>>>();
    cvt_split<<<(NM * NC) / 1024, 256>>>(x, xh, xl);
    wt_split<<<dim3(3 * NC / 32, NC / 32), dim3(32, 8)>>>(Wa, wah, wal, NC, 3 * NC);
    wt_split<<<dim3(NC / 32, NC / 32), dim3(32, 8)>>>(Wp, wph, wpl, NC, NC);

    // 1) QKV = x @ W_attn
    gemm_mma<<<dim3(3 * NC / 128, NM / 128), 128, gemm_smem>>>(
        xh, xl, wah, wal, qkv, NM, 3 * NC, NC);

    // 2) RoPE + split to bf16 hi/lo heads (table-driven, 2 elems/thread)
    rope_split<<<(NBH * NT * 32) / 256, 256>>>(qkv);

    // 3) Flash attention (causal) on tensor cores -> yh/yl
    flash_mma<<<dim3(NT / 128, NBH), 256, flash_smem>>>(
        qh, ql, kh, kl, vh, vl, yh, yl);

    // 4) out = y @ W_proj
    gemm_mma<<<dim3(NC / 128, NM / 128), 128, gemm_smem>>>(
        yh, yl, wph, wpl, out, NM, NC, NC);
}

// round 16
// speedup vs baseline: 1.8045x; 1.1474x over previous
#include <cuda_runtime.h>
#include <cuda_fp16.h>
#include <cuda_bf16.h>
#include <math.h>
#include <stdint.h>

#define NB 2
#define NT 2048
#define NC 1024
#define NH 16
#define ND 64
#define NBH (NB*NH)
#define NM (NB*NT)   // 4096 rows

// ---------------------------------------------------------------------------
// Scratch (static device allocations)
// ---------------------------------------------------------------------------
__device__ float g_qkv[(size_t)NM * 3 * NC];            // [4096, 3072]

__device__ __half g_xh[(size_t)NM * NC];                // x hi/lo (fp16)
__device__ __half g_xl[(size_t)NM * NC];
__device__ __half g_yh[(size_t)NM * NC];                // attn out hi/lo (fp16)
__device__ __half g_yl[(size_t)NM * NC];
__device__ __half g_wah[(size_t)(3*NC) * NC];           // Wa^T hi/lo [3072][1024]
__device__ __half g_wal[(size_t)(3*NC) * NC];
__device__ __half g_wph[(size_t)NC * NC];               // Wp^T hi/lo
__device__ __half g_wpl[(size_t)NC * NC];

__device__ __nv_bfloat16 g_qh[(size_t)NBH * NT * ND];   // RoPE'd Q*scale hi/lo (bf16)
__device__ __nv_bfloat16 g_ql[(size_t)NBH * NT * ND];
__device__ __nv_bfloat16 g_kh[(size_t)NBH * NT * ND];
__device__ __nv_bfloat16 g_kl[(size_t)NBH * NT * ND];
__device__ __nv_bfloat16 g_vh[(size_t)NBH * NT * ND];
__device__ __nv_bfloat16 g_vl[(size_t)NBH * NT * ND];

__device__ float g_cs[(size_t)NT * ND * 2];             // (cos,sin) per (t,d)

// ---------------------------------------------------------------------------
__device__ __forceinline__ uint32_t smem_u32(const void* p) {
    uint32_t a;
    asm("{ .reg .u64 t; cvta.to.shared.u64 t, %1; cvt.u32.u64 %0, t; }"
        : "=r"(a) : "l"(p));
    return a;
}
#define SWZ(o)   ((o) ^ (((o) >> 3) & 0x70))   // SW128 (128B rows)
#define SWZ64(o) ((o) ^ (((o) >> 3) & 0x30))   // SW64  (64B rows)

__device__ __forceinline__ void cpa16(uint32_t dst, const void* src) {
    asm volatile("cp.async.cg.shared.global [%0], [%1], 16;"
                 :: "r"(dst), "l"(src) : "memory");
}
#define CP_COMMIT() asm volatile("cp.async.commit_group;" ::: "memory")
#define CP_WAIT1()  asm volatile("cp.async.wait_group 1;" ::: "memory")
#define CP_WAIT0()  asm volatile("cp.async.wait_group 0;" ::: "memory")

__device__ __forceinline__ void ldsm4(uint32_t* r, uint32_t addr) {
    asm volatile("ldmatrix.sync.aligned.m8n8.x4.shared.b16 {%0,%1,%2,%3}, [%4];"
                 : "=r"(r[0]), "=r"(r[1]), "=r"(r[2]), "=r"(r[3]) : "r"(addr));
}
__device__ __forceinline__ void ldsm4t(uint32_t* r, uint32_t addr) {
    asm volatile("ldmatrix.sync.aligned.m8n8.x4.trans.shared.b16 {%0,%1,%2,%3}, [%4];"
                 : "=r"(r[0]), "=r"(r[1]), "=r"(r[2]), "=r"(r[3]) : "r"(addr));
}
// bf16 MMA (flash)
__device__ __forceinline__ void mma16816(float* d, const uint32_t* a, const uint32_t* b) {
    asm volatile(
        "mma.sync.aligned.m16n8k16.row.col.f32.bf16.bf16.f32 "
        "{%0,%1,%2,%3}, {%4,%5,%6,%7}, {%8,%9}, {%0,%1,%2,%3};"
        : "+f"(d[0]), "+f"(d[1]), "+f"(d[2]), "+f"(d[3])
        : "r"(a[0]), "r"(a[1]), "r"(a[2]), "r"(a[3]), "r"(b[0]), "r"(b[1]));
}
// fp16 MMA (dense GEMMs)
__device__ __forceinline__ void mma16816h(float* d, const uint32_t* a, const uint32_t* b) {
    asm volatile(
        "mma.sync.aligned.m16n8k16.row.col.f32.f16.f16.f32 "
        "{%0,%1,%2,%3}, {%4,%5,%6,%7}, {%8,%9}, {%0,%1,%2,%3};"
        : "+f"(d[0]), "+f"(d[1]), "+f"(d[2]), "+f"(d[3])
        : "r"(a[0]), "r"(a[1]), "r"(a[2]), "r"(a[3]), "r"(b[0]), "r"(b[1]));
}
__device__ __forceinline__ uint32_t packf(float lo, float hi) {   // bf16x2
    uint32_t d;
    asm("cvt.rn.bf16x2.f32 %0, %1, %2;" : "=r"(d) : "f"(hi), "f"(lo));
    return d;
}

// ---------------------------------------------------------------------------
// cos/sin table: g_cs[t][d] = {cos(t*f(d)), sin(t*f(d))}, freq dup over 32
// ---------------------------------------------------------------------------
__global__ void cs_init() {
    int idx = blockIdx.x * blockDim.x + threadIdx.x;   // over 2048*64
    int t = idx >> 6, d = idx & 63;
    int fi = d & 31;
    float inv = expf(-(float)fi * (9.210340371976184f / 32.0f));
    float sn, cs;
    sincosf((float)t * inv, &sn, &cs);
    g_cs[idx * 2 + 0] = cs;
    g_cs[idx * 2 + 1] = sn;
}

// ---------------------------------------------------------------------------
// Elementwise fp32 -> fp16 hi/lo split
// ---------------------------------------------------------------------------
__global__ void cvt_split(const float* __restrict__ in,
                          __half* __restrict__ h,
                          __half* __restrict__ l) {
    int i = (blockIdx.x * blockDim.x + threadIdx.x) * 4;
    float4 a = *(const float4*)(in + i);
    float v[4] = {a.x, a.y, a.z, a.w};
    __half hh[4], ll[4];
#pragma unroll
    for (int j = 0; j < 4; j++) {
        hh[j] = __float2half(v[j]);
        ll[j] = __float2half(v[j] - __half2float(hh[j]));
    }
    *(__half2*)(h + i)     = *(__half2*)&hh[0];
    *(__half2*)(h + i + 2) = *(__half2*)&hh[2];
    *(__half2*)(l + i)     = *(__half2*)&ll[0];
    *(__half2*)(l + i + 2) = *(__half2*)&ll[2];
}

// ---------------------------------------------------------------------------
// W [K][N] fp32 -> W^T hi/lo [N][K] fp16
// ---------------------------------------------------------------------------
__global__ void wt_split(const float* __restrict__ W,
                         __half* __restrict__ Th,
                         __half* __restrict__ Tl, int K, int N) {
    __shared__ float t[32][33];
    int n0 = blockIdx.x * 32, k0 = blockIdx.y * 32;
    int tx = threadIdx.x, ty0 = threadIdx.y;
#pragma unroll
    for (int i = 0; i < 4; i++) {
        int ty = ty0 + i * 8;
        t[ty][tx] = W[(size_t)(k0 + ty) * N + n0 + tx];
    }
    __syncthreads();
#pragma unroll
    for (int i = 0; i < 4; i++) {
        int ty = ty0 + i * 8;
        float a = t[tx][ty];
        __half h = __float2half(a);
        __half l = __float2half(a - __half2float(h));
        Th[(size_t)(n0 + ty) * K + k0 + tx] = h;
        Tl[(size_t)(n0 + ty) * K + k0 + tx] = l;
    }
}

// ---------------------------------------------------------------------------
// HMMA fp16x2 GEMM: C = A@B^T, A hi/lo fp16, B hi/lo fp16 [N][K].
// CTA 128x128, 4 warps (64x64 tiles), 3-stage cp.async, K-chunk 32, SW64.
// Passes per k16: Ah*Bh + Ah*Bl (Al*Bh dropped; fp16 residual ~1.4e-4 RMS).
// Stage = 3 tiles x 8KB (Ah, Bh, Bl) = 24KB.
// ---------------------------------------------------------------------------
__global__ __launch_bounds__(128, 2) void gemm_mma(
    const __half* __restrict__ Ah,
    const __half* __restrict__ Bh, const __half* __restrict__ Bl,
    float* __restrict__ C, int M, int N, int K) {
    extern __shared__ char smem[];
    const uint32_t sb = smem_u32(smem);   // stage s at sb + s*24576
    const int tid = threadIdx.x, wid = tid >> 5, lane = tid & 31;
    const int m0 = blockIdx.y * 128, n0 = blockIdx.x * 128;
    const int wm0 = (wid >> 1) * 64, wn0 = (wid & 1) * 64;

    const __half* bA0 = Ah + (size_t)m0 * K;
    const __half* bB0 = Bh + (size_t)n0 * K;
    const __half* bB1 = Bl + (size_t)n0 * K;

    uint32_t a_r[4], a_z[4];
#pragma unroll
    for (int i = 0; i < 4; i++) {
        int row = wm0 + 16 * i + (lane & 15);
        a_r[i] = row * 64;
        a_z[i] = (row & 6) << 3;
    }
    const uint32_t gA = (lane >> 4) * 16;
    uint32_t b_r[4], b_z[4];
#pragma unroll
    for (int j = 0; j < 4; j++) {
        int row = wn0 + 16 * j + (lane & 7) + ((lane >> 4) << 3);
        b_r[j] = row * 64;
        b_z[j] = (row & 6) << 3;
    }
    const uint32_t gB = ((lane >> 3) & 1) * 16;

    float acc[4][8][4];
#pragma unroll
    for (int i = 0; i < 4; i++)
#pragma unroll
        for (int j = 0; j < 8; j++)
#pragma unroll
            for (int q = 0; q < 4; q++) acc[i][j][q] = 0.f;

#define G_ISSUE(cc, ss)                                                        \
    do {                                                                       \
        const int k0_ = (cc) * 32;                                             \
        const uint32_t stb_ = sb + (ss) * 24576;                               \
        _Pragma("unroll")                                                      \
        for (int i_ = 0; i_ < 12; i_++) {                                      \
            const __half* base_ =                                              \
                (i_ >> 2) == 0 ? bA0 : (i_ >> 2) == 1 ? bB0 : bB1;             \
            int w_ = tid + (i_ & 3) * 128;                                     \
            int r_ = w_ >> 2, c4_ = w_ & 3;                                    \
            cpa16(stb_ + (i_ >> 2) * 8192 + SWZ64(r_ * 64 + c4_ * 16),         \
                  base_ + (size_t)r_ * K + k0_ + c4_ * 8);                     \
        }                                                                      \
        CP_COMMIT();                                                           \
    } while (0)

    const int nch = K / 32;
    G_ISSUE(0, 0);
    G_ISSUE(1, 1);
    int s = 0;
    for (int c = 0; c < nch; c++) {
        if (c + 1 < nch) CP_WAIT1(); else CP_WAIT0();
        __syncthreads();
        if (c + 2 < nch) G_ISSUE(c + 2, (s + 2) % 3);

        const uint32_t stb = sb + s * 24576;
#pragma unroll
        for (int ks = 0; ks < 2; ks++) {
            const uint32_t off = ks * 32;
            uint32_t af[4][4], bh2[4][4], bl2[4][4];
#pragma unroll
            for (int i = 0; i < 4; i++)
                ldsm4(af[i], stb + a_r[i] + ((off + gA) ^ a_z[i]));
#pragma unroll
            for (int j = 0; j < 4; j++) {
                ldsm4(bh2[j], stb + 8192  + b_r[j] + ((off + gB) ^ b_z[j]));
                ldsm4(bl2[j], stb + 16384 + b_r[j] + ((off + gB) ^ b_z[j]));
            }
            // pass 1: Ah * Bh
#pragma unroll
            for (int i = 0; i < 4; i++)
#pragma unroll
                for (int j = 0; j < 4; j++) {
                    mma16816h(acc[i][j * 2 + 0], af[i], &bh2[j][0]);
                    mma16816h(acc[i][j * 2 + 1], af[i], &bh2[j][2]);
                }
            // pass 2: Ah * Bl
#pragma unroll
            for (int i = 0; i < 4; i++)
#pragma unroll
                for (int j = 0; j < 4; j++) {
                    mma16816h(acc[i][j * 2 + 0], af[i], &bl2[j][0]);
                    mma16816h(acc[i][j * 2 + 1], af[i], &bl2[j][2]);
                }
        }
        s = (s + 1) % 3;
    }
#undef G_ISSUE

    const int er = lane >> 2, ec = (lane & 3) * 2;
#pragma unroll
    for (int i = 0; i < 4; i++) {
        int r = m0 + wm0 + 16 * i + er;
#pragma unroll
        for (int j = 0; j < 8; j++) {
            int col = n0 + wn0 + 8 * j + ec;
            *(float2*)(C + (size_t)r * N + col)       = make_float2(acc[i][j][0], acc[i][j][1]);
            *(float2*)(C + (size_t)(r + 8) * N + col) = make_float2(acc[i][j][2], acc[i][j][3]);
        }
    }
}

// ---------------------------------------------------------------------------
// RoPE + head split, table-driven, 2 elements per thread. Emits bf16 hi/lo.
// ---------------------------------------------------------------------------
__global__ void rope_split(const float* __restrict__ qkv)
{
    int idx = blockIdx.x * blockDim.x + threadIdx.x;  // over BH*T*32
    int p  = idx & 31;
    int t  = (idx >> 5) & (NT - 1);
    int bh = idx >> 16;
    int b = bh >> 4, h = bh & (NH - 1);
    int d0 = p * 2;
    int dmo = (d0 + 63) & 63;          // d0 - 1 (odd index, scalar load)
    const float* base = qkv + (size_t)(b * NT + t) * (3 * NC);
    int cq = h * ND;

    float2 q2 = *(const float2*)(base + cq + d0);
    float  qm = base[cq + dmo];
    float2 k2 = *(const float2*)(base + NC + cq + d0);
    float  km = base[NC + cq + dmo];
    float2 v2 = *(const float2*)(base + 2 * NC + cq + d0);

    float4 cs2 = *(const float4*)(g_cs + ((size_t)t * ND + d0) * 2); // c0,s0,c1,s1

    float rq0 = (q2.x * cs2.x + qm   * cs2.y) * 0.125f;
    float rq1 = (q2.y * cs2.z + q2.x * cs2.w) * 0.125f;
    float rk0 = k2.x * cs2.x + km   * cs2.y;
    float rk1 = k2.y * cs2.z + k2.x * cs2.w;

    size_t o = ((size_t)bh * NT + t) * ND + d0;
    uint32_t ph, pl;
    ph = packf(rq0, rq1);
    pl = packf(rq0 - __uint_as_float(ph << 16), rq1 - __uint_as_float(ph & 0xffff0000u));
    *(uint32_t*)(g_qh + o) = ph;
    *(uint32_t*)(g_ql + o) = pl;
    ph = packf(rk0, rk1);
    pl = packf(rk0 - __uint_as_float(ph << 16), rk1 - __uint_as_float(ph & 0xffff0000u));
    *(uint32_t*)(g_kh + o) = ph;
    *(uint32_t*)(g_kl + o) = pl;
    ph = packf(v2.x, v2.y);
    pl = packf(v2.x - __uint_as_float(ph << 16), v2.y - __uint_as_float(ph & 0xffff0000u));
    *(uint32_t*)(g_vh + o) = ph;
    *(uint32_t*)(g_vl + o) = pl;
}

// ---------------------------------------------------------------------------
// Flash attention on HMMA (bf16x3 internally), fp16 hi/lo output for proj.
// ---------------------------------------------------------------------------
__global__ __launch_bounds__(256, 2) void flash_mma(
    const __nv_bfloat16* __restrict__ Qh_, const __nv_bfloat16* __restrict__ Ql_,
    const __nv_bfloat16* __restrict__ Kh_, const __nv_bfloat16* __restrict__ Kl_,
    const __nv_bfloat16* __restrict__ Vh_, const __nv_bfloat16* __restrict__ Vl_,
    __half* __restrict__ Yh_, __half* __restrict__ Yl_)
{
    extern __shared__ char smem[];
    const uint32_t sb = smem_u32(smem);
    const uint32_t sQh = sb, sQl = sb + 16384;

    const int bh = blockIdx.y;
    const int qi = (gridDim.x - 1) - blockIdx.x;   // LPT: heaviest first
    const int q0 = qi * 128;
    const int tid = threadIdx.x, wid = tid >> 5, lane = tid & 31;
    const int wm = wid * 16;
    const size_t gbase = (size_t)bh * NT * ND;

    const __nv_bfloat16* pKh = Kh_ + gbase;
    const __nv_bfloat16* pKl = Kl_ + gbase;
    const __nv_bfloat16* pVh = Vh_ + gbase;
    const __nv_bfloat16* pVl = Vl_ + gbase;

    // ---- load Q hi/lo (128x64, SW128) ----
    {
        const __nv_bfloat16* s0 = Qh_ + gbase + (size_t)q0 * ND;
        const __nv_bfloat16* s1 = Ql_ + gbase + (size_t)q0 * ND;
#pragma unroll
        for (int i = 0; i < 4; i++) {
            int idx = tid + i * 256;
            int r = idx >> 3, c8 = idx & 7;
            uint32_t off = SWZ(r * 128 + c8 * 16);
            uint4 v = *(const uint4*)(s0 + (size_t)r * ND + c8 * 8);
            asm volatile("st.shared.v4.b32 [%0], {%1,%2,%3,%4};"
                         :: "r"(sQh + off), "r"(v.x), "r"(v.y), "r"(v.z), "r"(v.w));
            uint4 w = *(const uint4*)(s1 + (size_t)r * ND + c8 * 8);
            asm volatile("st.shared.v4.b32 [%0], {%1,%2,%3,%4};"
                         :: "r"(sQl + off), "r"(w.x), "r"(w.y), "r"(w.z), "r"(w.w));
        }
    }

#define F_ISSUE(kt_, ss)                                                       \
    do {                                                                       \
        const size_t ko_ = (size_t)(kt_) * 64 * ND;                            \
        const uint32_t kvb_ = sb + 32768 + (ss) * 32768;                       \
        _Pragma("unroll")                                                      \
        for (int i_ = 0; i_ < 8; i_++) {                                       \
            const __nv_bfloat16* base_ =                                       \
                (i_ >> 1) == 0 ? pKh : (i_ >> 1) == 1 ? pKl                    \
              : (i_ >> 1) == 2 ? pVh : pVl;                                    \
            int w_ = tid + (i_ & 1) * 256;                                     \
            int r_ = w_ >> 3, c8_ = w_ & 7;                                    \
            cpa16(kvb_ + (i_ >> 1) * 8192 + SWZ(r_ * 128 + c8_ * 16),          \
                  base_ + ko_ + (size_t)r_ * ND + c8_ * 8);                    \
        }                                                                      \
        CP_COMMIT();                                                           \
    } while (0)

    const int rowA = wm + (lane & 15);
    const uint32_t aoff = rowA * 128, aswz = (rowA & 7) * 16;
    const uint32_t gA = (lane >> 4) * 16;
    const int rowB_ = (lane & 7) + ((lane >> 4) << 3);
    const uint32_t bswz = (rowB_ & 7) * 16;
    const uint32_t gB = ((lane >> 3) & 1) * 16;
    const int rowV_ = ((lane >> 3) & 1) * 8 + (lane & 7);
    const uint32_t vswz = (lane & 7) * 16;
    const uint32_t gV = (lane >> 4) * 16;

    float m0 = -1e30f, m1 = -1e30f, l0 = 0.f, l1 = 0.f;
    float oacc[8][4];
#pragma unroll
    for (int j = 0; j < 8; j++)
#pragma unroll
        for (int e = 0; e < 4; e++) oacc[j][e] = 0.f;

    const int nkt = 2 * qi + 2;
    F_ISSUE(0, 0);
    for (int kt = 0; kt < nkt; kt++) {
        const int s = kt & 1;
        if (kt + 1 < nkt) { F_ISSUE(kt + 1, s ^ 1); CP_WAIT1(); }
        else              { CP_WAIT0(); }
        __syncthreads();

        const uint32_t kvb = sb + 32768 + s * 32768;
        const uint32_t sKh = kvb, sKl = kvb + 8192;
        const uint32_t sVh = kvb + 16384, sVl = kvb + 24576;

        if (kt * 64 <= q0 + wm + 15) {
            float sacc[8][4];
#pragma unroll
            for (int j = 0; j < 8; j++)
#pragma unroll
                for (int e = 0; e < 4; e++) sacc[j][e] = 0.f;

#pragma unroll
            for (int ks = 0; ks < 4; ks++) {
                const uint32_t ks32 = ks * 32;
                uint32_t aqh[4], aql[4];
                ldsm4(aqh, sQh + aoff + ((ks32 + gA) ^ aswz));
                ldsm4(aql, sQl + aoff + ((ks32 + gA) ^ aswz));
#pragma unroll
                for (int jb = 0; jb < 4; jb++) {
                    uint32_t roff = (jb * 16 + rowB_) * 128 + ((ks32 + gB) ^ bswz);
                    uint32_t kh4[4], kl4[4];
                    ldsm4(kh4, sKh + roff);
                    ldsm4(kl4, sKl + roff);
                    mma16816(sacc[2 * jb + 0], aqh, &kh4[0]);
                    mma16816(sacc[2 * jb + 1], aqh, &kh4[2]);
                    mma16816(sacc[2 * jb + 0], aqh, &kl4[0]);
                    mma16816(sacc[2 * jb + 1], aqh, &kl4[2]);
                    mma16816(sacc[2 * jb + 0], aql, &kh4[0]);
                    mma16816(sacc[2 * jb + 1], aql, &kh4[2]);
                }
            }

            if ((kt + 1) * 64 - 1 > q0 + wm) {
                const int rb = q0 + wm + (lane >> 2);
                const int cb = kt * 64 + (lane & 3) * 2;
#pragma unroll
                for (int t = 0; t < 8; t++) {
                    int c = cb + t * 8;
                    if (c     > rb)     sacc[t][0] = -1e30f;
                    if (c + 1 > rb)     sacc[t][1] = -1e30f;
                    if (c     > rb + 8) sacc[t][2] = -1e30f;
                    if (c + 1 > rb + 8) sacc[t][3] = -1e30f;
                }
            }

            {
                float mx0 = -1e30f, mx1 = -1e30f;
#pragma unroll
                for (int t = 0; t < 8; t++) {
                    mx0 = fmaxf(mx0, fmaxf(sacc[t][0], sacc[t][1]));
                    mx1 = fmaxf(mx1, fmaxf(sacc[t][2], sacc[t][3]));
                }
                mx0 = fmaxf(mx0, __shfl_xor_sync(0xffffffffu, mx0, 1));
                mx0 = fmaxf(mx0, __shfl_xor_sync(0xffffffffu, mx0, 2));
                mx1 = fmaxf(mx1, __shfl_xor_sync(0xffffffffu, mx1, 1));
                mx1 = fmaxf(mx1, __shfl_xor_sync(0xffffffffu, mx1, 2));
                float mn0 = fmaxf(m0, mx0), mn1 = fmaxf(m1, mx1);
                float a0 = __expf(m0 - mn0), a1 = __expf(m1 - mn1);
                m0 = mn0; m1 = mn1;
                float ls0 = 0.f, ls1 = 0.f;
#pragma unroll
                for (int t = 0; t < 8; t++) {
                    sacc[t][0] = __expf(sacc[t][0] - mn0);
                    sacc[t][1] = __expf(sacc[t][1] - mn0);
                    sacc[t][2] = __expf(sacc[t][2] - mn1);
                    sacc[t][3] = __expf(sacc[t][3] - mn1);
                    ls0 += sacc[t][0] + sacc[t][1];
                    ls1 += sacc[t][2] + sacc[t][3];
                }
                ls0 += __shfl_xor_sync(0xffffffffu, ls0, 1);
                ls0 += __shfl_xor_sync(0xffffffffu, ls0, 2);
                ls1 += __shfl_xor_sync(0xffffffffu, ls1, 1);
                ls1 += __shfl_xor_sync(0xffffffffu, ls1, 2);
                l0 = l0 * a0 + ls0;
                l1 = l1 * a1 + ls1;
#pragma unroll
                for (int j = 0; j < 8; j++) {
                    oacc[j][0] *= a0; oacc[j][1] *= a0;
                    oacc[j][2] *= a1; oacc[j][3] *= a1;
                }
            }

#pragma unroll
            for (int ks = 0; ks < 4; ks++) {
                uint32_t ah[4], al[4];
                ah[0] = packf(sacc[2*ks][0],   sacc[2*ks][1]);
                ah[1] = packf(sacc[2*ks][2],   sacc[2*ks][3]);
                ah[2] = packf(sacc[2*ks+1][0], sacc[2*ks+1][1]);
                ah[3] = packf(sacc[2*ks+1][2], sacc[2*ks+1][3]);
#pragma unroll
                for (int r = 0; r < 4; r++) {
                    float flo = __uint_as_float(ah[r] << 16);
                    float fhi = __uint_as_float(ah[r] & 0xffff0000u);
                    float s0 = sacc[2*ks + (r >> 1)][(r & 1) * 2 + 0];
                    float s1 = sacc[2*ks + (r >> 1)][(r & 1) * 2 + 1];
                    al[r] = packf(s0 - flo, s1 - fhi);
                }
                const uint32_t vrow = (ks * 16 + rowV_) * 128;
#pragma unroll
                for (int jb = 0; jb < 4; jb++) {
                    uint32_t voff = vrow + ((jb * 32 + gV) ^ vswz);
                    uint32_t vh4[4], vl4[4];
                    ldsm4t(vh4, sVh + voff);
                    ldsm4t(vl4, sVl + voff);
                    mma16816(oacc[2 * jb + 0], ah, &vh4[0]);
                    mma16816(oacc[2 * jb + 1], ah, &vh4[2]);
                    mma16816(oacc[2 * jb + 0], ah, &vl4[0]);
                    mma16816(oacc[2 * jb + 1], ah, &vl4[2]);
                    mma16816(oacc[2 * jb + 0], al, &vh4[0]);
                    mma16816(oacc[2 * jb + 1], al, &vh4[2]);
                }
            }
        }
        __syncthreads();
    }
#undef F_ISSUE

    // ---- epilogue: normalize, fp16 hi/lo split, write [b,t,h*64+d] ----
    {
        const int b = bh >> 4, h = bh & (NH - 1);
        const float i0 = 1.f / l0, i1 = 1.f / l1;
        const int t0 = q0 + wm + (lane >> 2);
        const int c0 = h * ND + (lane & 3) * 2;
#pragma unroll
        for (int j = 0; j < 8; j++) {
            float v0 = oacc[j][0] * i0, v1 = oacc[j][1] * i0;
            float v2 = oacc[j][2] * i1, v3 = oacc[j][3] * i1;
            __half2 h0 = __floats2half2_rn(v0, v1);
            __half2 h1 = __floats2half2_rn(v2, v3);
            __half2 e0 = __floats2half2_rn(v0 - __half2float(__low2half(h0)),
                                           v1 - __half2float(__high2half(h0)));
            __half2 e1 = __floats2half2_rn(v2 - __half2float(__low2half(h1)),
                                           v3 - __half2float(__high2half(h1)));
            size_t o0 = (size_t)(b * NT + t0) * NC + c0 + j * 8;
            size_t o1 = (size_t)(b * NT + t0 + 8) * NC + c0 + j * 8;
            *(__half2*)(Yh_ + o0) = h0;
            *(__half2*)(Yl_ + o0) = e0;
            *(__half2*)(Yh_ + o1) = h1;
            *(__half2*)(Yl_ + o1) = e1;
        }
    }
}

// ---------------------------------------------------------------------------
extern "C" void kernel_launch(void* const* d_in, const int* in_sizes, int n_in,
                              void* d_out, int out_size)
{
    const float* x  = (const float*)d_in[0];
    const float* Wa = (const float*)d_in[1];
    const float* Wp = (const float*)d_in[2];
    float* out = (float*)d_out;

    float* qkv;
    __half *xh, *xl, *yh, *yl, *wah, *wal, *wph, *wpl;
    __nv_bfloat16 *qh, *ql, *kh, *kl, *vh, *vl;
    cudaGetSymbolAddress((void**)&qkv, g_qkv);
    cudaGetSymbolAddress((void**)&xh,  g_xh);
    cudaGetSymbolAddress((void**)&xl,  g_xl);
    cudaGetSymbolAddress((void**)&yh,  g_yh);
    cudaGetSymbolAddress((void**)&yl,  g_yl);
    cudaGetSymbolAddress((void**)&wah, g_wah);
    cudaGetSymbolAddress((void**)&wal, g_wal);
    cudaGetSymbolAddress((void**)&wph, g_wph);
    cudaGetSymbolAddress((void**)&wpl, g_wpl);
    cudaGetSymbolAddress((void**)&qh,  g_qh);
    cudaGetSymbolAddress((void**)&ql,  g_ql);
    cudaGetSymbolAddress((void**)&kh,  g_kh);
    cudaGetSymbolAddress((void**)&kl,  g_kl);
    cudaGetSymbolAddress((void**)&vh,  g_vh);
    cudaGetSymbolAddress((void**)&vl,  g_vl);

    const int gemm_smem = 73728;          // 3 stages x 24KB
    cudaFuncSetAttribute(gemm_mma, cudaFuncAttributeMaxDynamicSharedMemorySize, gemm_smem);
    const int flash_smem = 98304;         // Q 32KB + 2 stages x 32KB
    cudaFuncSetAttribute(flash_mma, cudaFuncAttributeMaxDynamicSharedMemorySize, flash_smem);

    // 0) cos/sin table, input splits, weight transposes (fp16)
    cs_init<<<(NT * ND) / 256, 256>>>();
    cvt_split<<<(NM * NC) / 1024, 256>>>(x, xh, xl);
    wt_split<<<dim3(3 * NC / 32, NC / 32), dim3(32, 8)>>>(Wa, wah, wal, NC, 3 * NC);
    wt_split<<<dim3(NC / 32, NC / 32), dim3(32, 8)>>>(Wp, wph, wpl, NC, NC);

    // 1) QKV = x @ W_attn  (fp16x2)
    gemm_mma<<<dim3(3 * NC / 128, NM / 128), 128, gemm_smem>>>(
        xh, wah, wal, qkv, NM, 3 * NC, NC);

    // 2) RoPE + split to bf16 hi/lo heads
    rope_split<<<(NBH * NT * 32) / 256, 256>>>(qkv);

    // 3) Flash attention (causal, bf16x3) -> y fp16 hi/lo
    flash_mma<<<dim3(NT / 128, NBH), 256, flash_smem>>>(
        qh, ql, kh, kl, vh, vl, yh, yl);

    // 4) out = y @ W_proj  (fp16x2)
    gemm_mma<<<dim3(NC / 128, NM / 128), 128, gemm_smem>>>(
        yh, wph, wpl, out, NM, NC, NC);
}

// round 17
// speedup vs baseline: 2.1550x; 1.1943x over previous
#include <cuda_runtime.h>
#include <cuda_fp16.h>
#include <math.h>
#include <stdint.h>

#define NB 2
#define NT 2048
#define NC 1024
#define NH 16
#define ND 64
#define NBH (NB*NH)
#define NM (NB*NT)   // 4096 rows

// ---------------------------------------------------------------------------
// Scratch (static device allocations)
// ---------------------------------------------------------------------------
__device__ float g_qkv[(size_t)NM * 3 * NC];            // [4096, 3072]

__device__ __half g_xh[(size_t)NM * NC];                // x hi/lo (fp16)
__device__ __half g_xl[(size_t)NM * NC];
__device__ __half g_yh[(size_t)NM * NC];                // attn out hi/lo (fp16)
__device__ __half g_yl[(size_t)NM * NC];
__device__ __half g_wah[(size_t)(3*NC) * NC];           // Wa^T hi/lo [3072][1024]
__device__ __half g_wal[(size_t)(3*NC) * NC];
__device__ __half g_wph[(size_t)NC * NC];               // Wp^T hi/lo
__device__ __half g_wpl[(size_t)NC * NC];

__device__ __half g_qh[(size_t)NBH * NT * ND];          // RoPE'd Q*scale (fp16 hi only)
__device__ __half g_kh[(size_t)NBH * NT * ND];          // K hi/lo
__device__ __half g_kl[(size_t)NBH * NT * ND];
__device__ __half g_vh[(size_t)NBH * NT * ND];          // V hi/lo
__device__ __half g_vl[(size_t)NBH * NT * ND];

__device__ float g_cs[(size_t)NT * ND * 2];             // (cos,sin) per (t,d)

// ---------------------------------------------------------------------------
__device__ __forceinline__ uint32_t smem_u32(const void* p) {
    uint32_t a;
    asm("{ .reg .u64 t; cvta.to.shared.u64 t, %1; cvt.u32.u64 %0, t; }"
        : "=r"(a) : "l"(p));
    return a;
}
#define SWZ(o)   ((o) ^ (((o) >> 3) & 0x70))   // SW128 (128B rows)
#define SWZ64(o) ((o) ^ (((o) >> 3) & 0x30))   // SW64  (64B rows)

__device__ __forceinline__ void cpa16(uint32_t dst, const void* src) {
    asm volatile("cp.async.cg.shared.global [%0], [%1], 16;"
                 :: "r"(dst), "l"(src) : "memory");
}
#define CP_COMMIT() asm volatile("cp.async.commit_group;" ::: "memory")
#define CP_WAIT1()  asm volatile("cp.async.wait_group 1;" ::: "memory")
#define CP_WAIT0()  asm volatile("cp.async.wait_group 0;" ::: "memory")

__device__ __forceinline__ void ldsm4(uint32_t* r, uint32_t addr) {
    asm volatile("ldmatrix.sync.aligned.m8n8.x4.shared.b16 {%0,%1,%2,%3}, [%4];"
                 : "=r"(r[0]), "=r"(r[1]), "=r"(r[2]), "=r"(r[3]) : "r"(addr));
}
__device__ __forceinline__ void ldsm4t(uint32_t* r, uint32_t addr) {
    asm volatile("ldmatrix.sync.aligned.m8n8.x4.trans.shared.b16 {%0,%1,%2,%3}, [%4];"
                 : "=r"(r[0]), "=r"(r[1]), "=r"(r[2]), "=r"(r[3]) : "r"(addr));
}
// fp16 MMA
__device__ __forceinline__ void mma16816h(float* d, const uint32_t* a, const uint32_t* b) {
    asm volatile(
        "mma.sync.aligned.m16n8k16.row.col.f32.f16.f16.f32 "
        "{%0,%1,%2,%3}, {%4,%5,%6,%7}, {%8,%9}, {%0,%1,%2,%3};"
        : "+f"(d[0]), "+f"(d[1]), "+f"(d[2]), "+f"(d[3])
        : "r"(a[0]), "r"(a[1]), "r"(a[2]), "r"(a[3]), "r"(b[0]), "r"(b[1]));
}
__device__ __forceinline__ uint32_t packh(float lo, float hi) {   // fp16x2
    __half2 h = __floats2half2_rn(lo, hi);
    return *(uint32_t*)&h;
}

// ---------------------------------------------------------------------------
// cos/sin table: g_cs[t][d] = {cos(t*f(d)), sin(t*f(d))}, freq dup over 32
// ---------------------------------------------------------------------------
__global__ void cs_init() {
    int idx = blockIdx.x * blockDim.x + threadIdx.x;   // over 2048*64
    int t = idx >> 6, d = idx & 63;
    int fi = d & 31;
    float inv = expf(-(float)fi * (9.210340371976184f / 32.0f));
    float sn, cs;
    sincosf((float)t * inv, &sn, &cs);
    g_cs[idx * 2 + 0] = cs;
    g_cs[idx * 2 + 1] = sn;
}

// ---------------------------------------------------------------------------
// Elementwise fp32 -> fp16 hi/lo split
// ---------------------------------------------------------------------------
__global__ void cvt_split(const float* __restrict__ in,
                          __half* __restrict__ h,
                          __half* __restrict__ l) {
    int i = (blockIdx.x * blockDim.x + threadIdx.x) * 4;
    float4 a = *(const float4*)(in + i);
    float v[4] = {a.x, a.y, a.z, a.w};
    __half hh[4], ll[4];
#pragma unroll
    for (int j = 0; j < 4; j++) {
        hh[j] = __float2half(v[j]);
        ll[j] = __float2half(v[j] - __half2float(hh[j]));
    }
    *(__half2*)(h + i)     = *(__half2*)&hh[0];
    *(__half2*)(h + i + 2) = *(__half2*)&hh[2];
    *(__half2*)(l + i)     = *(__half2*)&ll[0];
    *(__half2*)(l + i + 2) = *(__half2*)&ll[2];
}

// ---------------------------------------------------------------------------
// W [K][N] fp32 -> W^T hi/lo [N][K] fp16
// ---------------------------------------------------------------------------
__global__ void wt_split(const float* __restrict__ W,
                         __half* __restrict__ Th,
                         __half* __restrict__ Tl, int K, int N) {
    __shared__ float t[32][33];
    int n0 = blockIdx.x * 32, k0 = blockIdx.y * 32;
    int tx = threadIdx.x, ty0 = threadIdx.y;
#pragma unroll
    for (int i = 0; i < 4; i++) {
        int ty = ty0 + i * 8;
        t[ty][tx] = W[(size_t)(k0 + ty) * N + n0 + tx];
    }
    __syncthreads();
#pragma unroll
    for (int i = 0; i < 4; i++) {
        int ty = ty0 + i * 8;
        float a = t[tx][ty];
        __half h = __float2half(a);
        __half l = __float2half(a - __half2float(h));
        Th[(size_t)(n0 + ty) * K + k0 + tx] = h;
        Tl[(size_t)(n0 + ty) * K + k0 + tx] = l;
    }
}

// ---------------------------------------------------------------------------
// HMMA fp16x2 GEMM: C = A@B^T, A hi fp16, B hi/lo fp16 [N][K].
// CTA 128x128, 4 warps (64x64 tiles), 3-stage cp.async, K-chunk 32, SW64.
// Passes per k16: Ah*Bh + Ah*Bl. Stage = 3 tiles x 8KB = 24KB.
// ---------------------------------------------------------------------------
__global__ __launch_bounds__(128, 2) void gemm_mma(
    const __half* __restrict__ Ah,
    const __half* __restrict__ Bh, const __half* __restrict__ Bl,
    float* __restrict__ C, int M, int N, int K) {
    extern __shared__ char smem[];
    const uint32_t sb = smem_u32(smem);   // stage s at sb + s*24576
    const int tid = threadIdx.x, wid = tid >> 5, lane = tid & 31;
    const int m0 = blockIdx.y * 128, n0 = blockIdx.x * 128;
    const int wm0 = (wid >> 1) * 64, wn0 = (wid & 1) * 64;

    const __half* bA0 = Ah + (size_t)m0 * K;
    const __half* bB0 = Bh + (size_t)n0 * K;
    const __half* bB1 = Bl + (size_t)n0 * K;

    uint32_t a_r[4], a_z[4];
#pragma unroll
    for (int i = 0; i < 4; i++) {
        int row = wm0 + 16 * i + (lane & 15);
        a_r[i] = row * 64;
        a_z[i] = (row & 6) << 3;
    }
    const uint32_t gA = (lane >> 4) * 16;
    uint32_t b_r[4], b_z[4];
#pragma unroll
    for (int j = 0; j < 4; j++) {
        int row = wn0 + 16 * j + (lane & 7) + ((lane >> 4) << 3);
        b_r[j] = row * 64;
        b_z[j] = (row & 6) << 3;
    }
    const uint32_t gB = ((lane >> 3) & 1) * 16;

    float acc[4][8][4];
#pragma unroll
    for (int i = 0; i < 4; i++)
#pragma unroll
        for (int j = 0; j < 8; j++)
#pragma unroll
            for (int q = 0; q < 4; q++) acc[i][j][q] = 0.f;

#define G_ISSUE(cc, ss)                                                        \
    do {                                                                       \
        const int k0_ = (cc) * 32;                                             \
        const uint32_t stb_ = sb + (ss) * 24576;                               \
        _Pragma("unroll")                                                      \
        for (int i_ = 0; i_ < 12; i_++) {                                      \
            const __half* base_ =                                              \
                (i_ >> 2) == 0 ? bA0 : (i_ >> 2) == 1 ? bB0 : bB1;             \
            int w_ = tid + (i_ & 3) * 128;                                     \
            int r_ = w_ >> 2, c4_ = w_ & 3;                                    \
            cpa16(stb_ + (i_ >> 2) * 8192 + SWZ64(r_ * 64 + c4_ * 16),         \
                  base_ + (size_t)r_ * K + k0_ + c4_ * 8);                     \
        }                                                                      \
        CP_COMMIT();                                                           \
    } while (0)

    const int nch = K / 32;
    G_ISSUE(0, 0);
    G_ISSUE(1, 1);
    int s = 0;
    for (int c = 0; c < nch; c++) {
        if (c + 1 < nch) CP_WAIT1(); else CP_WAIT0();
        __syncthreads();
        if (c + 2 < nch) G_ISSUE(c + 2, (s + 2) % 3);

        const uint32_t stb = sb + s * 24576;
#pragma unroll
        for (int ks = 0; ks < 2; ks++) {
            const uint32_t off = ks * 32;
            uint32_t af[4][4], bh2[4][4], bl2[4][4];
#pragma unroll
            for (int i = 0; i < 4; i++)
                ldsm4(af[i], stb + a_r[i] + ((off + gA) ^ a_z[i]));
#pragma unroll
            for (int j = 0; j < 4; j++) {
                ldsm4(bh2[j], stb + 8192  + b_r[j] + ((off + gB) ^ b_z[j]));
                ldsm4(bl2[j], stb + 16384 + b_r[j] + ((off + gB) ^ b_z[j]));
            }
#pragma unroll
            for (int i = 0; i < 4; i++)
#pragma unroll
                for (int j = 0; j < 4; j++) {
                    mma16816h(acc[i][j * 2 + 0], af[i], &bh2[j][0]);
                    mma16816h(acc[i][j * 2 + 1], af[i], &bh2[j][2]);
                }
#pragma unroll
            for (int i = 0; i < 4; i++)
#pragma unroll
                for (int j = 0; j < 4; j++) {
                    mma16816h(acc[i][j * 2 + 0], af[i], &bl2[j][0]);
                    mma16816h(acc[i][j * 2 + 1], af[i], &bl2[j][2]);
                }
        }
        s = (s + 1) % 3;
    }
#undef G_ISSUE

    const int er = lane >> 2, ec = (lane & 3) * 2;
#pragma unroll
    for (int i = 0; i < 4; i++) {
        int r = m0 + wm0 + 16 * i + er;
#pragma unroll
        for (int j = 0; j < 8; j++) {
            int col = n0 + wn0 + 8 * j + ec;
            *(float2*)(C + (size_t)r * N + col)       = make_float2(acc[i][j][0], acc[i][j][1]);
            *(float2*)(C + (size_t)(r + 8) * N + col) = make_float2(acc[i][j][2], acc[i][j][3]);
        }
    }
}

// ---------------------------------------------------------------------------
// RoPE + head split, table-driven, 2 elems/thread. Emits fp16:
// Q hi only (lo dropped in flash), K hi/lo, V hi/lo.
// ---------------------------------------------------------------------------
__global__ void rope_split(const float* __restrict__ qkv)
{
    int idx = blockIdx.x * blockDim.x + threadIdx.x;  // over BH*T*32
    int p  = idx & 31;
    int t  = (idx >> 5) & (NT - 1);
    int bh = idx >> 16;
    int b = bh >> 4, h = bh & (NH - 1);
    int d0 = p * 2;
    int dmo = (d0 + 63) & 63;
    const float* base = qkv + (size_t)(b * NT + t) * (3 * NC);
    int cq = h * ND;

    float2 q2 = *(const float2*)(base + cq + d0);
    float  qm = base[cq + dmo];
    float2 k2 = *(const float2*)(base + NC + cq + d0);
    float  km = base[NC + cq + dmo];
    float2 v2 = *(const float2*)(base + 2 * NC + cq + d0);

    float4 cs2 = *(const float4*)(g_cs + ((size_t)t * ND + d0) * 2);

    float rq0 = (q2.x * cs2.x + qm   * cs2.y) * 0.125f;
    float rq1 = (q2.y * cs2.z + q2.x * cs2.w) * 0.125f;
    float rk0 = k2.x * cs2.x + km   * cs2.y;
    float rk1 = k2.y * cs2.z + k2.x * cs2.w;

    size_t o = ((size_t)bh * NT + t) * ND + d0;
    *(uint32_t*)(g_qh + o) = packh(rq0, rq1);
    uint32_t kh = packh(rk0, rk1);
    *(uint32_t*)(g_kh + o) = kh;
    __half2 kh2 = *(__half2*)&kh;
    *(uint32_t*)(g_kl + o) = packh(rk0 - __half2float(__low2half(kh2)),
                                   rk1 - __half2float(__high2half(kh2)));
    uint32_t vh = packh(v2.x, v2.y);
    *(uint32_t*)(g_vh + o) = vh;
    __half2 vh2 = *(__half2*)&vh;
    *(uint32_t*)(g_vl + o) = packh(v2.x - __half2float(__low2half(vh2)),
                                   v2.y - __half2float(__high2half(vh2)));
}

// ---------------------------------------------------------------------------
// Flash attention, fp16x2: S = Qh*(Kh+Kl); O += Ph*(Vh+Vl).
// smem: Qh 16KB @ sb; KV stages 32KB each @ sb+16384 + s*32768.
// ---------------------------------------------------------------------------
__global__ __launch_bounds__(256, 2) void flash_mma(
    const __half* __restrict__ Qh_,
    const __half* __restrict__ Kh_, const __half* __restrict__ Kl_,
    const __half* __restrict__ Vh_, const __half* __restrict__ Vl_,
    __half* __restrict__ Yh_, __half* __restrict__ Yl_)
{
    extern __shared__ char smem[];
    const uint32_t sb = smem_u32(smem);
    const uint32_t sQh = sb;

    const int bh = blockIdx.y;
    const int qi = (gridDim.x - 1) - blockIdx.x;   // LPT
    const int q0 = qi * 128;
    const int tid = threadIdx.x, wid = tid >> 5, lane = tid & 31;
    const int wm = wid * 16;
    const size_t gbase = (size_t)bh * NT * ND;

    const __half* pKh = Kh_ + gbase;
    const __half* pKl = Kl_ + gbase;
    const __half* pVh = Vh_ + gbase;
    const __half* pVl = Vl_ + gbase;

    // ---- load Qh (128x64, SW128) ----
    {
        const __half* s0 = Qh_ + gbase + (size_t)q0 * ND;
#pragma unroll
        for (int i = 0; i < 4; i++) {
            int idx = tid + i * 256;
            int r = idx >> 3, c8 = idx & 7;
            uint32_t off = SWZ(r * 128 + c8 * 16);
            uint4 v = *(const uint4*)(s0 + (size_t)r * ND + c8 * 8);
            asm volatile("st.shared.v4.b32 [%0], {%1,%2,%3,%4};"
                         :: "r"(sQh + off), "r"(v.x), "r"(v.y), "r"(v.z), "r"(v.w));
        }
    }

#define F_ISSUE(kt_, ss)                                                       \
    do {                                                                       \
        const size_t ko_ = (size_t)(kt_) * 64 * ND;                            \
        const uint32_t kvb_ = sb + 16384 + (ss) * 32768;                       \
        _Pragma("unroll")                                                      \
        for (int i_ = 0; i_ < 8; i_++) {                                       \
            const __half* base_ =                                              \
                (i_ >> 1) == 0 ? pKh : (i_ >> 1) == 1 ? pKl                    \
              : (i_ >> 1) == 2 ? pVh : pVl;                                    \
            int w_ = tid + (i_ & 1) * 256;                                     \
            int r_ = w_ >> 3, c8_ = w_ & 7;                                    \
            cpa16(kvb_ + (i_ >> 1) * 8192 + SWZ(r_ * 128 + c8_ * 16),          \
                  base_ + ko_ + (size_t)r_ * ND + c8_ * 8);                    \
        }                                                                      \
        CP_COMMIT();                                                           \
    } while (0)

    const int rowA = wm + (lane & 15);
    const uint32_t aoff = rowA * 128, aswz = (rowA & 7) * 16;
    const uint32_t gA = (lane >> 4) * 16;
    const int rowB_ = (lane & 7) + ((lane >> 4) << 3);
    const uint32_t bswz = (rowB_ & 7) * 16;
    const uint32_t gB = ((lane >> 3) & 1) * 16;
    const int rowV_ = ((lane >> 3) & 1) * 8 + (lane & 7);
    const uint32_t vswz = (lane & 7) * 16;
    const uint32_t gV = (lane >> 4) * 16;

    float m0 = -1e30f, m1 = -1e30f, l0 = 0.f, l1 = 0.f;
    float oacc[8][4];
#pragma unroll
    for (int j = 0; j < 8; j++)
#pragma unroll
        for (int e = 0; e < 4; e++) oacc[j][e] = 0.f;

    const int nkt = 2 * qi + 2;
    F_ISSUE(0, 0);
    for (int kt = 0; kt < nkt; kt++) {
        const int s = kt & 1;
        if (kt + 1 < nkt) { F_ISSUE(kt + 1, s ^ 1); CP_WAIT1(); }
        else              { CP_WAIT0(); }
        __syncthreads();

        const uint32_t kvb = sb + 16384 + s * 32768;
        const uint32_t sKh = kvb, sKl = kvb + 8192;
        const uint32_t sVh = kvb + 16384, sVl = kvb + 24576;

        if (kt * 64 <= q0 + wm + 15) {
            // ---- S = Qh (Kh + Kl) ----
            float sacc[8][4];
#pragma unroll
            for (int j = 0; j < 8; j++)
#pragma unroll
                for (int e = 0; e < 4; e++) sacc[j][e] = 0.f;

#pragma unroll
            for (int ks = 0; ks < 4; ks++) {
                const uint32_t ks32 = ks * 32;
                uint32_t aqh[4];
                ldsm4(aqh, sQh + aoff + ((ks32 + gA) ^ aswz));
#pragma unroll
                for (int jb = 0; jb < 4; jb++) {
                    uint32_t roff = (jb * 16 + rowB_) * 128 + ((ks32 + gB) ^ bswz);
                    uint32_t kh4[4], kl4[4];
                    ldsm4(kh4, sKh + roff);
                    ldsm4(kl4, sKl + roff);
                    mma16816h(sacc[2 * jb + 0], aqh, &kh4[0]);
                    mma16816h(sacc[2 * jb + 1], aqh, &kh4[2]);
                    mma16816h(sacc[2 * jb + 0], aqh, &kl4[0]);
                    mma16816h(sacc[2 * jb + 1], aqh, &kl4[2]);
                }
            }

            if ((kt + 1) * 64 - 1 > q0 + wm) {
                const int rb = q0 + wm + (lane >> 2);
                const int cb = kt * 64 + (lane & 3) * 2;
#pragma unroll
                for (int t = 0; t < 8; t++) {
                    int c = cb + t * 8;
                    if (c     > rb)     sacc[t][0] = -1e30f;
                    if (c + 1 > rb)     sacc[t][1] = -1e30f;
                    if (c     > rb + 8) sacc[t][2] = -1e30f;
                    if (c + 1 > rb + 8) sacc[t][3] = -1e30f;
                }
            }

            {
                float mx0 = -1e30f, mx1 = -1e30f;
#pragma unroll
                for (int t = 0; t < 8; t++) {
                    mx0 = fmaxf(mx0, fmaxf(sacc[t][0], sacc[t][1]));
                    mx1 = fmaxf(mx1, fmaxf(sacc[t][2], sacc[t][3]));
                }
                mx0 = fmaxf(mx0, __shfl_xor_sync(0xffffffffu, mx0, 1));
                mx0 = fmaxf(mx0, __shfl_xor_sync(0xffffffffu, mx0, 2));
                mx1 = fmaxf(mx1, __shfl_xor_sync(0xffffffffu, mx1, 1));
                mx1 = fmaxf(mx1, __shfl_xor_sync(0xffffffffu, mx1, 2));
                float mn0 = fmaxf(m0, mx0), mn1 = fmaxf(m1, mx1);
                float a0 = __expf(m0 - mn0), a1 = __expf(m1 - mn1);
                m0 = mn0; m1 = mn1;
                float ls0 = 0.f, ls1 = 0.f;
#pragma unroll
                for (int t = 0; t < 8; t++) {
                    sacc[t][0] = __expf(sacc[t][0] - mn0);
                    sacc[t][1] = __expf(sacc[t][1] - mn0);
                    sacc[t][2] = __expf(sacc[t][2] - mn1);
                    sacc[t][3] = __expf(sacc[t][3] - mn1);
                    ls0 += sacc[t][0] + sacc[t][1];
                    ls1 += sacc[t][2] + sacc[t][3];
                }
                ls0 += __shfl_xor_sync(0xffffffffu, ls0, 1);
                ls0 += __shfl_xor_sync(0xffffffffu, ls0, 2);
                ls1 += __shfl_xor_sync(0xffffffffu, ls1, 1);
                ls1 += __shfl_xor_sync(0xffffffffu, ls1, 2);
                l0 = l0 * a0 + ls0;
                l1 = l1 * a1 + ls1;
#pragma unroll
                for (int j = 0; j < 8; j++) {
                    oacc[j][0] *= a0; oacc[j][1] *= a0;
                    oacc[j][2] *= a1; oacc[j][3] *= a1;
                }
            }

            // ---- O += Ph (Vh + Vl) ----
#pragma unroll
            for (int ks = 0; ks < 4; ks++) {
                uint32_t ah[4];
                ah[0] = packh(sacc[2*ks][0],   sacc[2*ks][1]);
                ah[1] = packh(sacc[2*ks][2],   sacc[2*ks][3]);
                ah[2] = packh(sacc[2*ks+1][0], sacc[2*ks+1][1]);
                ah[3] = packh(sacc[2*ks+1][2], sacc[2*ks+1][3]);
                const uint32_t vrow = (ks * 16 + rowV_) * 128;
#pragma unroll
                for (int jb = 0; jb < 4; jb++) {
                    uint32_t voff = vrow + ((jb * 32 + gV) ^ vswz);
                    uint32_t vh4[4], vl4[4];
                    ldsm4t(vh4, sVh + voff);
                    ldsm4t(vl4, sVl + voff);
                    mma16816h(oacc[2 * jb + 0], ah, &vh4[0]);
                    mma16816h(oacc[2 * jb + 1], ah, &vh4[2]);
                    mma16816h(oacc[2 * jb + 0], ah, &vl4[0]);
                    mma16816h(oacc[2 * jb + 1], ah, &vl4[2]);
                }
            }
        }
        __syncthreads();
    }
#undef F_ISSUE

    // ---- epilogue: normalize, fp16 hi/lo split, write [b,t,h*64+d] ----
    {
        const int b = bh >> 4, h = bh & (NH - 1);
        const float i0 = 1.f / l0, i1 = 1.f / l1;
        const int t0 = q0 + wm + (lane >> 2);
        const int c0 = h * ND + (lane & 3) * 2;
#pragma unroll
        for (int j = 0; j < 8; j++) {
            float v0 = oacc[j][0] * i0, v1 = oacc[j][1] * i0;
            float v2 = oacc[j][2] * i1, v3 = oacc[j][3] * i1;
            __half2 h0 = __floats2half2_rn(v0, v1);
            __half2 h1 = __floats2half2_rn(v2, v3);
            __half2 e0 = __floats2half2_rn(v0 - __half2float(__low2half(h0)),
                                           v1 - __half2float(__high2half(h0)));
            __half2 e1 = __floats2half2_rn(v2 - __half2float(__low2half(h1)),
                                           v3 - __half2float(__high2half(h1)));
            size_t o0 = (size_t)(b * NT + t0) * NC + c0 + j * 8;
            size_t o1 = (size_t)(b * NT + t0 + 8) * NC + c0 + j * 8;
            *(__half2*)(Yh_ + o0) = h0;
            *(__half2*)(Yl_ + o0) = e0;
            *(__half2*)(Yh_ + o1) = h1;
            *(__half2*)(Yl_ + o1) = e1;
        }
    }
}

// ---------------------------------------------------------------------------
extern "C" void kernel_launch(void* const* d_in, const int* in_sizes, int n_in,
                              void* d_out, int out_size)
{
    const float* x  = (const float*)d_in[0];
    const float* Wa = (const float*)d_in[1];
    const float* Wp = (const float*)d_in[2];
    float* out = (float*)d_out;

    float* qkv;
    __half *xh, *xl, *yh, *yl, *wah, *wal, *wph, *wpl;
    __half *qh, *kh, *kl, *vh, *vl;
    cudaGetSymbolAddress((void**)&qkv, g_qkv);
    cudaGetSymbolAddress((void**)&xh,  g_xh);
    cudaGetSymbolAddress((void**)&xl,  g_xl);
    cudaGetSymbolAddress((void**)&yh,  g_yh);
    cudaGetSymbolAddress((void**)&yl,  g_yl);
    cudaGetSymbolAddress((void**)&wah, g_wah);
    cudaGetSymbolAddress((void**)&wal, g_wal);
    cudaGetSymbolAddress((void**)&wph, g_wph);
    cudaGetSymbolAddress((void**)&wpl, g_wpl);
    cudaGetSymbolAddress((void**)&qh,  g_qh);
    cudaGetSymbolAddress((void**)&kh,  g_kh);
    cudaGetSymbolAddress((void**)&kl,  g_kl);
    cudaGetSymbolAddress((void**)&vh,  g_vh);
    cudaGetSymbolAddress((void**)&vl,  g_vl);

    const int gemm_smem = 73728;          // 3 stages x 24KB
    cudaFuncSetAttribute(gemm_mma, cudaFuncAttributeMaxDynamicSharedMemorySize, gemm_smem);
    const int flash_smem = 81920;         // Qh 16KB + 2 stages x 32KB
    cudaFuncSetAttribute(flash_mma, cudaFuncAttributeMaxDynamicSharedMemorySize, flash_smem);

    // 0) cos/sin table, input splits, weight transposes (fp16)
    cs_init<<<(NT * ND) / 256, 256>>>();
    cvt_split<<<(NM * NC) / 1024, 256>>>(x, xh, xl);
    wt_split<<<dim3(3 * NC / 32, NC / 32), dim3(32, 8)>>>(Wa, wah, wal, NC, 3 * NC);
    wt_split<<<dim3(NC / 32, NC / 32), dim3(32, 8)>>>(Wp, wph, wpl, NC, NC);

    // 1) QKV = x @ W_attn  (fp16x2)
    gemm_mma<<<dim3(3 * NC / 128, NM / 128), 128, gemm_smem>>>(
        xh, wah, wal, qkv, NM, 3 * NC, NC);

    // 2) RoPE + split to fp16 heads
    rope_split<<<(NBH * NT * 32) / 256, 256>>>(qkv);

    // 3) Flash attention (causal, fp16x2) -> y fp16 hi/lo
    flash_mma<<<dim3(NT / 128, NBH), 256, flash_smem>>>(
        qh, kh, kl, vh, vl, yh, yl);

    // 4) out = y @ W_proj  (fp16x2)
    gemm_mma<<<dim3(NC / 128, NM / 128), 128, gemm_smem>>>(
        yh, wph, wpl, out, NM, NC, NC);
}